// round 1
// baseline (speedup 1.0000x reference)
#include <cuda_runtime.h>
#include <cuda_bf16.h>

#define NA    900
#define EMBED 256
#define NG    8
#define NCAM  6
#define NLVL  4
#define NPTS  13
#define NJ    312          // NCAM*NLVL*NPTS
#define NW    2496         // NJ*NG

// pyramid geometry (per level): H, W, HW, and pixel offset of level start
// (each level region holds all 6 cameras: [cam][y][x][ch])
#define HW0 11264
#define HW1 2816
#define HW2 704
#define HW3 176
#define LOFF0 0
#define LOFF1 67584        // 6*HW0
#define LOFF2 84480        // + 6*HW1
#define LOFF3 88704        // + 6*HW2
#define TOTPX 89760        // + 6*HW3
#define FMT_ELEMS (TOTPX * EMBED)   // 22,978,560

// ---------------- scratch (device globals; no dynamic allocation) ----------
__device__ __nv_bfloat16 g_fmT[FMT_ELEMS];      // ~46 MB channel-last bf16 pyramid
__device__ float  g_logits[NA * NW];            // weight logits -> softmaxed in place
__device__ float2 g_uv[NA * NCAM * NPTS];       // normalized grid coords per (a,c,p)
__device__ float  g_fused[NA * EMBED];          // fused features pre output-proj

// ---------------- 1) transpose (C,H,W) f32 -> (px, C) bf16 -----------------
__global__ void k_transpose(const float* __restrict__ fm, int HW, int loff) {
    __shared__ float tile[32][33];
    const int c   = blockIdx.z;
    const int ch0 = blockIdx.y * 32;
    const int px0 = blockIdx.x * 32;
    const int tx = threadIdx.x, ty = threadIdx.y;

    int px = px0 + tx;
    if (px < HW)
        tile[ty][tx] = fm[(c * EMBED + ch0 + ty) * HW + px];
    __syncthreads();
    int pw = px0 + ty;
    if (pw < HW)
        g_fmT[(loff + c * HW + pw) * EMBED + ch0 + tx] =
            __float2bfloat16_rn(tile[tx][ty]);
}

// ---------------- 2) project key points -> normalized grid coords ----------
__global__ void k_uv(const float* __restrict__ kp,
                     const float* __restrict__ proj,
                     const float* __restrict__ wh) {
    int idx = blockIdx.x * blockDim.x + threadIdx.x;
    if (idx >= NA * NCAM * NPTS) return;
    int p = idx % NPTS;
    int c = (idx / NPTS) % NCAM;
    int a = idx / (NPTS * NCAM);

    const float* k3 = kp + (a * NPTS + p) * 3;
    float x = k3[0], y = k3[1], z = k3[2];
    const float* M = proj + c * 16;
    float px = M[0]*x + M[1]*y + M[2]*z  + M[3];
    float py = M[4]*x + M[5]*y + M[6]*z  + M[7];
    float pd = M[8]*x + M[9]*y + M[10]*z + M[11];
    pd = fmaxf(pd, 1e-5f);
    float u = (px / pd) / wh[c*2+0] * 2.f - 1.f;
    float v = (py / pd) / wh[c*2+1] * 2.f - 1.f;
    g_uv[idx] = make_float2(u, v);
}

// ---------------- 3) weight GEMM: (inst+anchor)[900x256] @ W[256x2496] -----
#define BM 64
#define BN 64
#define BK 16
__global__ __launch_bounds__(256) void k_gemm1(const float* __restrict__ inst,
                                               const float* __restrict__ anch,
                                               const float* __restrict__ W,
                                               const float* __restrict__ bias) {
    __shared__ float As[BM][BK];
    __shared__ float Bs[BK][BN];
    const int tid = threadIdx.x;
    const int tx = tid & 15, ty = tid >> 4;
    const int n0 = blockIdx.x * BN;
    const int a0 = blockIdx.y * BM;

    float acc[4][4] = {};
    for (int k0 = 0; k0 < EMBED; k0 += BK) {
        // load A tile (feat = inst + anchor), float4 per thread
        {
            int row = tid >> 2;
            int c4  = (tid & 3) * 4;
            float4 v = make_float4(0.f, 0.f, 0.f, 0.f);
            int ga = a0 + row;
            if (ga < NA) {
                float4 i4 = *(const float4*)(inst + ga * EMBED + k0 + c4);
                float4 a4 = *(const float4*)(anch + ga * EMBED + k0 + c4);
                v = make_float4(i4.x + a4.x, i4.y + a4.y, i4.z + a4.z, i4.w + a4.w);
            }
            *(float4*)&As[row][c4] = v;
        }
        // load B tile
        {
            int brow = tid >> 4;
            int bc4  = (tid & 15) * 4;
            *(float4*)&Bs[brow][bc4] =
                *(const float4*)(W + (k0 + brow) * NW + n0 + bc4);
        }
        __syncthreads();
        #pragma unroll
        for (int kk = 0; kk < BK; kk++) {
            float rm[4];
            #pragma unroll
            for (int i = 0; i < 4; i++) rm[i] = As[ty * 4 + i][kk];
            float4 rn = *(float4*)&Bs[kk][tx * 4];
            float rnv[4] = {rn.x, rn.y, rn.z, rn.w};
            #pragma unroll
            for (int i = 0; i < 4; i++)
                #pragma unroll
                for (int j = 0; j < 4; j++)
                    acc[i][j] += rm[i] * rnv[j];
        }
        __syncthreads();
    }
    #pragma unroll
    for (int i = 0; i < 4; i++) {
        int a = a0 + ty * 4 + i;
        if (a >= NA) continue;
        #pragma unroll
        for (int j = 0; j < 4; j++) {
            int n = n0 + tx * 4 + j;
            g_logits[a * NW + n] = acc[i][j] + bias[n];
        }
    }
}

// ---------------- 4) per-(anchor,group) softmax over 312 entries -----------
__global__ __launch_bounds__(256) void k_softmax() {
    const int a = blockIdx.x;
    const int g = threadIdx.x >> 5;      // warp = group
    const int lane = threadIdx.x & 31;
    float* L = g_logits + a * NW;

    float mx = -1e30f;
    for (int j = lane; j < NJ; j += 32) mx = fmaxf(mx, L[j * NG + g]);
    #pragma unroll
    for (int o = 16; o; o >>= 1) mx = fmaxf(mx, __shfl_xor_sync(0xffffffffu, mx, o));

    float vals[10];
    float sum = 0.f;
    int cnt = 0;
    for (int j = lane; j < NJ; j += 32) {
        float e = __expf(L[j * NG + g] - mx);
        vals[cnt++] = e;
        sum += e;
    }
    #pragma unroll
    for (int o = 16; o; o >>= 1) sum += __shfl_xor_sync(0xffffffffu, sum, o);
    float inv = 1.f / sum;
    cnt = 0;
    for (int j = lane; j < NJ; j += 32) L[j * NG + g] = vals[cnt++] * inv;
}

// ---------------- 5) bilinear sampling + weighted fusion -------------------
// 1 block = 1 anchor; thread = output channel; acc is a single register.
__global__ __launch_bounds__(256) void k_sample() {
    __shared__ float  s_w[NW];               // softmaxed weights for this anchor
    __shared__ float2 s_uv[NCAM * NPTS];
    const int a = blockIdx.x;
    const int tid = threadIdx.x;

    for (int i = tid; i < NW; i += 256) s_w[i] = g_logits[a * NW + i];
    if (tid < NCAM * NPTS) s_uv[tid] = g_uv[a * NCAM * NPTS + tid];
    __syncthreads();

    const int g = tid >> 5;
    const int Ws[4]   = {176, 88, 44, 22};
    const int Hs[4]   = {64, 32, 16, 8};
    const int HWs[4]  = {HW0, HW1, HW2, HW3};
    const int LOFF[4] = {LOFF0, LOFF1, LOFF2, LOFF3};

    float acc = 0.f;
    for (int c = 0; c < NCAM; c++) {
        for (int p = 0; p < NPTS; p++) {
            float2 uv = s_uv[c * NPTS + p];
            #pragma unroll
            for (int l = 0; l < NLVL; l++) {
                float gx = (uv.x + 1.f) * (Ws[l] * 0.5f) - 0.5f;
                float gy = (uv.y + 1.f) * (Hs[l] * 0.5f) - 0.5f;
                float x0f = floorf(gx), y0f = floorf(gy);
                float wx1 = gx - x0f,  wy1 = gy - y0f;
                float wx0 = 1.f - wx1, wy0 = 1.f - wy1;
                int x0 = (int)x0f, y0 = (int)y0f;
                bool vx0 = (x0f >= 0.f)       && (x0f <= (float)(Ws[l] - 1));
                bool vx1 = (x0f + 1.f >= 0.f) && (x0f + 1.f <= (float)(Ws[l] - 1));
                bool vy0 = (y0f >= 0.f)       && (y0f <= (float)(Hs[l] - 1));
                bool vy1 = (y0f + 1.f >= 0.f) && (y0f + 1.f <= (float)(Hs[l] - 1));

                const __nv_bfloat16* base =
                    g_fmT + (LOFF[l] + c * HWs[l]) * EMBED + tid;
                const int rs = Ws[l] * EMBED;
                float v00 = 0.f, v01 = 0.f, v10 = 0.f, v11 = 0.f;
                if (vy0) {
                    const __nv_bfloat16* r0 = base + y0 * rs;
                    if (vx0) v00 = __bfloat162float(__ldg(r0 + x0 * EMBED));
                    if (vx1) v01 = __bfloat162float(__ldg(r0 + (x0 + 1) * EMBED));
                }
                if (vy1) {
                    const __nv_bfloat16* r1 = base + (y0 + 1) * rs;
                    if (vx0) v10 = __bfloat162float(__ldg(r1 + x0 * EMBED));
                    if (vx1) v11 = __bfloat162float(__ldg(r1 + (x0 + 1) * EMBED));
                }
                float bil = (v00 * wx0 + v01 * wx1) * wy0
                          + (v10 * wx0 + v11 * wx1) * wy1;
                acc += s_w[((c * NLVL + l) * NPTS + p) * NG + g] * bil;
            }
        }
    }
    g_fused[a * EMBED + tid] = acc;
}

// ---------------- 6) output proj + bias + residual -------------------------
#define FBM 6   // 900/6 = 150 blocks
__global__ __launch_bounds__(256) void k_final(const float* __restrict__ inst,
                                               const float* __restrict__ Wout,
                                               const float* __restrict__ bout,
                                               float* __restrict__ out) {
    __shared__ float s_f[FBM][EMBED];
    const int a0 = blockIdx.x * FBM;
    const int tid = threadIdx.x;
    for (int i = tid; i < FBM * EMBED; i += 256)
        s_f[i / EMBED][i % EMBED] = g_fused[(a0 + i / EMBED) * EMBED + (i % EMBED)];
    __syncthreads();

    float acc[FBM] = {};
    const int j = tid;
    for (int k = 0; k < EMBED; k++) {
        float wv = Wout[k * EMBED + j];
        #pragma unroll
        for (int r = 0; r < FBM; r++) acc[r] += s_f[r][k] * wv;
    }
    #pragma unroll
    for (int r = 0; r < FBM; r++) {
        int a = a0 + r;
        out[a * EMBED + j] = acc[r] + bout[j] + inst[a * EMBED + j];
    }
}

// ---------------- launch ---------------------------------------------------
extern "C" void kernel_launch(void* const* d_in, const int* in_sizes, int n_in,
                              void* d_out, int out_size) {
    const float* inst = (const float*)d_in[0];
    const float* anch = (const float*)d_in[1];
    const float* kp   = (const float*)d_in[2];
    const float* fm0  = (const float*)d_in[3];
    const float* fm1  = (const float*)d_in[4];
    const float* fm2  = (const float*)d_in[5];
    const float* fm3  = (const float*)d_in[6];
    const float* proj = (const float*)d_in[7];
    const float* wh   = (const float*)d_in[8];
    const float* Ww   = (const float*)d_in[9];
    const float* bw   = (const float*)d_in[10];
    const float* Wo   = (const float*)d_in[11];
    const float* bo   = (const float*)d_in[12];
    float* out = (float*)d_out;

    dim3 tb(32, 32);
    k_transpose<<<dim3((HW0 + 31) / 32, 8, NCAM), tb>>>(fm0, HW0, LOFF0);
    k_transpose<<<dim3((HW1 + 31) / 32, 8, NCAM), tb>>>(fm1, HW1, LOFF1);
    k_transpose<<<dim3((HW2 + 31) / 32, 8, NCAM), tb>>>(fm2, HW2, LOFF2);
    k_transpose<<<dim3((HW3 + 31) / 32, 8, NCAM), tb>>>(fm3, HW3, LOFF3);

    k_uv<<<(NA * NCAM * NPTS + 255) / 256, 256>>>(kp, proj, wh);

    k_gemm1<<<dim3(NW / BN, (NA + BM - 1) / BM), 256>>>(inst, anch, Ww, bw);
    k_softmax<<<NA, 256>>>();
    k_sample<<<NA, 256>>>();
    k_final<<<NA / FBM, 256>>>(inst, Wo, bo, out);
}

// round 2
// speedup vs baseline: 1.2952x; 1.2952x over previous
#include <cuda_runtime.h>
#include <cuda_bf16.h>

#define NA    900
#define EMBED 256
#define NG    8
#define NCAM  6
#define NLVL  4
#define NPTS  13
#define NJ    312          // NCAM*NLVL*NPTS
#define NW    2496         // NJ*NG

#define HW0 11264
#define HW1 2816
#define HW2 704
#define HW3 176
#define LOFF0 0
#define LOFF1 67584        // 6*HW0
#define LOFF2 84480        // + 6*HW1
#define LOFF3 88704        // + 6*HW2
#define TOTPX 89760
#define FMT_ELEMS (TOTPX * EMBED)

// ---------------- scratch ----------------
__device__ __nv_bfloat16 g_fmT[FMT_ELEMS];      // channel-last bf16 pyramid (~46MB, L2-resident)
__device__ float  g_logits[NA * NW];
__device__ float2 g_uv[NA * NCAM * NPTS];
__device__ float  g_fused[NA * EMBED];

// ---------------- 1) transpose (C,H,W) f32 -> (px, C) bf16 -----------------
// tile: 32 px x 64 ch. smem [px][ch] padded -> conflict-free read phase,
// write phase emits bfloat162 (128B per warp-row).
__global__ void k_transpose(const float* __restrict__ fm, int HW, int loff) {
    __shared__ float tile[32][65];
    const int c   = blockIdx.z;
    const int ch0 = blockIdx.y * 64;
    const int px0 = blockIdx.x * 32;
    const int tx = threadIdx.x, ty = threadIdx.y;

    int px = px0 + tx;
    if (px < HW) {
        tile[tx][ty]      = fm[(c * EMBED + ch0 + ty) * HW + px];
        tile[tx][ty + 32] = fm[(c * EMBED + ch0 + ty + 32) * HW + px];
    }
    __syncthreads();
    int pw = px0 + ty;     // warp ty handles one pixel row
    if (pw < HW) {
        __nv_bfloat162 v = __floats2bfloat162_rn(tile[ty][2 * tx],
                                                 tile[ty][2 * tx + 1]);
        *(__nv_bfloat162*)(g_fmT + (size_t)(loff + c * HW + pw) * EMBED
                           + ch0 + 2 * tx) = v;
    }
}

// ---------------- 2) project key points ------------------------------------
__global__ void k_uv(const float* __restrict__ kp,
                     const float* __restrict__ proj,
                     const float* __restrict__ wh) {
    int idx = blockIdx.x * blockDim.x + threadIdx.x;
    if (idx >= NA * NCAM * NPTS) return;
    int p = idx % NPTS;
    int c = (idx / NPTS) % NCAM;
    int a = idx / (NPTS * NCAM);

    const float* k3 = kp + (a * NPTS + p) * 3;
    float x = k3[0], y = k3[1], z = k3[2];
    const float* M = proj + c * 16;
    float px = M[0]*x + M[1]*y + M[2]*z  + M[3];
    float py = M[4]*x + M[5]*y + M[6]*z  + M[7];
    float pd = M[8]*x + M[9]*y + M[10]*z + M[11];
    pd = fmaxf(pd, 1e-5f);
    float u = (px / pd) / wh[c*2+0] * 2.f - 1.f;
    float v = (py / pd) / wh[c*2+1] * 2.f - 1.f;
    g_uv[idx] = make_float2(u, v);
}

// ---------------- 3) weight GEMM (conflict-free smem) ----------------------
#define BM 64
#define BN 64
#define BK 16
__global__ __launch_bounds__(256) void k_gemm1(const float* __restrict__ inst,
                                               const float* __restrict__ anch,
                                               const float* __restrict__ W,
                                               const float* __restrict__ bias) {
    __shared__ float As[BK][BM + 4];   // transposed: [k][m]
    __shared__ float Bs[BK][BN];
    const int tid = threadIdx.x;
    const int tx = tid & 15, ty = tid >> 4;
    const int n0 = blockIdx.x * BN;
    const int a0 = blockIdx.y * BM;

    float acc[4][4] = {};
    for (int k0 = 0; k0 < EMBED; k0 += BK) {
        {   // A tile: feat = inst + anchor, scatter transposed
            int row = tid >> 2;
            int c4  = (tid & 3) * 4;
            float4 v = make_float4(0.f, 0.f, 0.f, 0.f);
            int ga = a0 + row;
            if (ga < NA) {
                float4 i4 = *(const float4*)(inst + ga * EMBED + k0 + c4);
                float4 a4 = *(const float4*)(anch + ga * EMBED + k0 + c4);
                v = make_float4(i4.x + a4.x, i4.y + a4.y, i4.z + a4.z, i4.w + a4.w);
            }
            As[c4 + 0][row] = v.x;
            As[c4 + 1][row] = v.y;
            As[c4 + 2][row] = v.z;
            As[c4 + 3][row] = v.w;
        }
        {
            int brow = tid >> 4;
            int bc4  = (tid & 15) * 4;
            *(float4*)&Bs[brow][bc4] =
                *(const float4*)(W + (k0 + brow) * NW + n0 + bc4);
        }
        __syncthreads();
        #pragma unroll
        for (int kk = 0; kk < BK; kk++) {
            float4 rm4 = *(float4*)&As[kk][ty * 4];
            float4 rn4 = *(float4*)&Bs[kk][tx * 4];
            float rm[4] = {rm4.x, rm4.y, rm4.z, rm4.w};
            float rn[4] = {rn4.x, rn4.y, rn4.z, rn4.w};
            #pragma unroll
            for (int i = 0; i < 4; i++)
                #pragma unroll
                for (int j = 0; j < 4; j++)
                    acc[i][j] += rm[i] * rn[j];
        }
        __syncthreads();
    }
    #pragma unroll
    for (int i = 0; i < 4; i++) {
        int a = a0 + ty * 4 + i;
        if (a >= NA) continue;
        #pragma unroll
        for (int j = 0; j < 4; j++) {
            int n = n0 + tx * 4 + j;
            g_logits[a * NW + n] = acc[i][j] + bias[n];
        }
    }
}

// ---------------- 4) softmax: smem-staged, coalesced gmem ------------------
__global__ __launch_bounds__(256) void k_softmax() {
    __shared__ float s[NG][NJ + 1];
    const int a = blockIdx.x;
    const int tid = threadIdx.x;
    float4* L4 = (float4*)(g_logits + a * NW);

    for (int t = tid; t < NW / 4; t += 256) {
        float4 v = L4[t];
        int i0 = t * 4;
        s[(i0 + 0) & 7][(i0 + 0) >> 3] = v.x;
        s[(i0 + 1) & 7][(i0 + 1) >> 3] = v.y;
        s[(i0 + 2) & 7][(i0 + 2) >> 3] = v.z;
        s[(i0 + 3) & 7][(i0 + 3) >> 3] = v.w;
    }
    __syncthreads();

    const int g = tid >> 5, lane = tid & 31;
    float mx = -1e30f;
    for (int j = lane; j < NJ; j += 32) mx = fmaxf(mx, s[g][j]);
    #pragma unroll
    for (int o = 16; o; o >>= 1) mx = fmaxf(mx, __shfl_xor_sync(0xffffffffu, mx, o));
    float sum = 0.f;
    for (int j = lane; j < NJ; j += 32) {
        float e = __expf(s[g][j] - mx);
        s[g][j] = e;
        sum += e;
    }
    #pragma unroll
    for (int o = 16; o; o >>= 1) sum += __shfl_xor_sync(0xffffffffu, sum, o);
    float inv = 1.f / sum;
    for (int j = lane; j < NJ; j += 32) s[g][j] *= inv;
    __syncthreads();

    for (int t = tid; t < NW / 4; t += 256) {
        int i0 = t * 4;
        float4 v;
        v.x = s[(i0 + 0) & 7][(i0 + 0) >> 3];
        v.y = s[(i0 + 1) & 7][(i0 + 1) >> 3];
        v.z = s[(i0 + 2) & 7][(i0 + 2) >> 3];
        v.w = s[(i0 + 3) & 7][(i0 + 3) >> 3];
        L4[t] = v;
    }
}

// ---------------- 5) sampling: 4 anchors/block, 4 ch/thread (8B loads) -----
__global__ __launch_bounds__(256) void k_sample() {
    __shared__ float2 s_uv[4][NCAM * NPTS];
    const int tid = threadIdx.x;
    const int sub = tid >> 6;          // anchor within block
    const int lane = tid & 63;
    const int a = blockIdx.x * 4 + sub;
    const int ch = lane * 4;
    const int g = ch >> 5;

    for (int i = tid; i < 4 * NCAM * NPTS; i += 256) {
        int aa = i / (NCAM * NPTS), r = i % (NCAM * NPTS);
        s_uv[aa][r] = g_uv[(blockIdx.x * 4 + aa) * (NCAM * NPTS) + r];
    }
    __syncthreads();

    const int Wl[4]   = {176, 88, 44, 22};
    const int Hl[4]   = {64, 32, 16, 8};
    const int HWl[4]  = {HW0, HW1, HW2, HW3};
    const int LOFF[4] = {LOFF0, LOFF1, LOFF2, LOFF3};
    const float* wbase = g_logits + a * NW + g;

    float acc0 = 0.f, acc1 = 0.f, acc2 = 0.f, acc3 = 0.f;
    for (int c = 0; c < NCAM; c++) {
        for (int p = 0; p < NPTS; p++) {
            float2 uv = s_uv[sub][c * NPTS + p];
            #pragma unroll
            for (int l = 0; l < NLVL; l++) {
                float gx = (uv.x + 1.f) * (Wl[l] * 0.5f) - 0.5f;
                float gy = (uv.y + 1.f) * (Hl[l] * 0.5f) - 0.5f;
                float x0f = floorf(gx), y0f = floorf(gy);
                float wx1 = gx - x0f,  wy1 = gy - y0f;
                float wx0 = 1.f - wx1, wy0 = 1.f - wy1;
                int x0 = (int)x0f, y0 = (int)y0f;
                bool vx0 = (x0f >= 0.f)       && (x0f <= (float)(Wl[l] - 1));
                bool vx1 = (x0f + 1.f >= 0.f) && (x0f + 1.f <= (float)(Wl[l] - 1));
                bool vy0 = (y0f >= 0.f)       && (y0f <= (float)(Hl[l] - 1));
                bool vy1 = (y0f + 1.f >= 0.f) && (y0f + 1.f <= (float)(Hl[l] - 1));

                const __nv_bfloat16* base =
                    g_fmT + (size_t)(LOFF[l] + c * HWl[l]) * EMBED + ch;
                const int rs = Wl[l] * EMBED;
                uint2 q00 = {0u,0u}, q01 = {0u,0u}, q10 = {0u,0u}, q11 = {0u,0u};
                if (vy0) {
                    const __nv_bfloat16* r0 = base + y0 * rs;
                    if (vx0) q00 = __ldg((const uint2*)(r0 + x0 * EMBED));
                    if (vx1) q01 = __ldg((const uint2*)(r0 + (x0 + 1) * EMBED));
                }
                if (vy1) {
                    const __nv_bfloat16* r1 = base + (y0 + 1) * rs;
                    if (vx0) q10 = __ldg((const uint2*)(r1 + x0 * EMBED));
                    if (vx1) q11 = __ldg((const uint2*)(r1 + (x0 + 1) * EMBED));
                }
                float w = __ldg(wbase + ((c * NLVL + l) * NPTS + p) * NG);
                float w00 = wx0 * wy0 * w, w01 = wx1 * wy0 * w;
                float w10 = wx0 * wy1 * w, w11 = wx1 * wy1 * w;

                float2 a00 = __bfloat1622float2(*(__nv_bfloat162*)&q00.x);
                float2 b00 = __bfloat1622float2(*(__nv_bfloat162*)&q00.y);
                float2 a01 = __bfloat1622float2(*(__nv_bfloat162*)&q01.x);
                float2 b01 = __bfloat1622float2(*(__nv_bfloat162*)&q01.y);
                float2 a10 = __bfloat1622float2(*(__nv_bfloat162*)&q10.x);
                float2 b10 = __bfloat1622float2(*(__nv_bfloat162*)&q10.y);
                float2 a11 = __bfloat1622float2(*(__nv_bfloat162*)&q11.x);
                float2 b11 = __bfloat1622float2(*(__nv_bfloat162*)&q11.y);

                acc0 += w00 * a00.x + w01 * a01.x + w10 * a10.x + w11 * a11.x;
                acc1 += w00 * a00.y + w01 * a01.y + w10 * a10.y + w11 * a11.y;
                acc2 += w00 * b00.x + w01 * b01.x + w10 * b10.x + w11 * b11.x;
                acc3 += w00 * b00.y + w01 * b01.y + w10 * b10.y + w11 * b11.y;
            }
        }
    }
    float4 r = make_float4(acc0, acc1, acc2, acc3);
    *(float4*)(g_fused + a * EMBED + ch) = r;
}

// ---------------- 6) output proj + bias + residual -------------------------
#define FBM 6
__global__ __launch_bounds__(256) void k_final(const float* __restrict__ inst,
                                               const float* __restrict__ Wout,
                                               const float* __restrict__ bout,
                                               float* __restrict__ out) {
    __shared__ float s_f[FBM][EMBED];
    const int a0 = blockIdx.x * FBM;
    const int tid = threadIdx.x;
    for (int i = tid; i < FBM * EMBED; i += 256)
        s_f[i / EMBED][i % EMBED] = g_fused[(a0 + i / EMBED) * EMBED + (i % EMBED)];
    __syncthreads();

    float acc[FBM] = {};
    const int j = tid;
    #pragma unroll 4
    for (int k = 0; k < EMBED; k++) {
        float wv = Wout[k * EMBED + j];
        #pragma unroll
        for (int r = 0; r < FBM; r++) acc[r] += s_f[r][k] * wv;
    }
    #pragma unroll
    for (int r = 0; r < FBM; r++) {
        int a = a0 + r;
        out[a * EMBED + j] = acc[r] + bout[j] + inst[a * EMBED + j];
    }
}

// ---------------- launch ---------------------------------------------------
extern "C" void kernel_launch(void* const* d_in, const int* in_sizes, int n_in,
                              void* d_out, int out_size) {
    const float* inst = (const float*)d_in[0];
    const float* anch = (const float*)d_in[1];
    const float* kp   = (const float*)d_in[2];
    const float* fm0  = (const float*)d_in[3];
    const float* fm1  = (const float*)d_in[4];
    const float* fm2  = (const float*)d_in[5];
    const float* fm3  = (const float*)d_in[6];
    const float* proj = (const float*)d_in[7];
    const float* wh   = (const float*)d_in[8];
    const float* Ww   = (const float*)d_in[9];
    const float* bw   = (const float*)d_in[10];
    const float* Wo   = (const float*)d_in[11];
    const float* bo   = (const float*)d_in[12];
    float* out = (float*)d_out;

    dim3 tb(32, 32);
    k_transpose<<<dim3((HW0 + 31) / 32, 4, NCAM), tb>>>(fm0, HW0, LOFF0);
    k_transpose<<<dim3((HW1 + 31) / 32, 4, NCAM), tb>>>(fm1, HW1, LOFF1);
    k_transpose<<<dim3((HW2 + 31) / 32, 4, NCAM), tb>>>(fm2, HW2, LOFF2);
    k_transpose<<<dim3((HW3 + 31) / 32, 4, NCAM), tb>>>(fm3, HW3, LOFF3);

    k_uv<<<(NA * NCAM * NPTS + 255) / 256, 256>>>(kp, proj, wh);

    k_gemm1<<<dim3(NW / BN, (NA + BM - 1) / BM), 256>>>(inst, anch, Ww, bw);
    k_softmax<<<NA, 256>>>();
    k_sample<<<NA / 4, 256>>>();
    k_final<<<NA / FBM, 256>>>(inst, Wo, bo, out);
}

// round 3
// speedup vs baseline: 1.5195x; 1.1732x over previous
#include <cuda_runtime.h>
#include <cuda_bf16.h>

#define NA    900
#define EMBED 256
#define NG    8
#define NCAM  6
#define NLVL  4
#define NPTS  13
#define NJ    312
#define NW    2496

#define HW0 11264
#define HW1 2816
#define HW2 704
#define HW3 176
#define LOFF0 0
#define LOFF1 67584
#define LOFF2 84480
#define LOFF3 88704
#define TOTPX 89760
#define FMT_ELEMS (TOTPX * EMBED)

// px-block counts per level (32 px per block)
#define PB0 352
#define PB1 88
#define PB2 22
#define PB3 6
#define PBTOT 468

// ---------------- scratch ----------------
__device__ __nv_bfloat16 g_fmT[FMT_ELEMS];   // channel-last bf16 pyramid
__device__ float g_logits[NA * NW];          // raw logits (softmax done in k_sample smem)
__device__ float g_fused[NA * EMBED];

// ---------------- 1) fused transpose: all 4 levels, one launch -------------
__global__ void k_transpose(const float* __restrict__ fm0,
                            const float* __restrict__ fm1,
                            const float* __restrict__ fm2,
                            const float* __restrict__ fm3) {
    __shared__ float tile[32][65];
    int bx = blockIdx.x;
    const float* fm;
    int HW, loff;
    if (bx < PB0)                  { fm = fm0; HW = HW0; loff = LOFF0; }
    else if (bx < PB0 + PB1)       { fm = fm1; HW = HW1; loff = LOFF1; bx -= PB0; }
    else if (bx < PB0 + PB1 + PB2) { fm = fm2; HW = HW2; loff = LOFF2; bx -= PB0 + PB1; }
    else                           { fm = fm3; HW = HW3; loff = LOFF3; bx -= PB0 + PB1 + PB2; }

    const int c   = blockIdx.z;
    const int ch0 = blockIdx.y * 64;
    const int px0 = bx * 32;
    const int tx = threadIdx.x, ty = threadIdx.y;

    int px = px0 + tx;
    if (px < HW) {
        tile[tx][ty]      = fm[(c * EMBED + ch0 + ty) * HW + px];
        tile[tx][ty + 32] = fm[(c * EMBED + ch0 + ty + 32) * HW + px];
    }
    __syncthreads();
    int pw = px0 + ty;
    if (pw < HW) {
        __nv_bfloat162 v = __floats2bfloat162_rn(tile[ty][2 * tx],
                                                 tile[ty][2 * tx + 1]);
        *(__nv_bfloat162*)(g_fmT + (size_t)(loff + c * HW + pw) * EMBED
                           + ch0 + 2 * tx) = v;
    }
}

// ---------------- 2) weight GEMM: 128x128x8 tiles, 8x8 per thread ----------
#define BM 128
#define BN 128
#define BK 8
__global__ __launch_bounds__(256) void k_gemm1(const float* __restrict__ inst,
                                               const float* __restrict__ anch,
                                               const float* __restrict__ W,
                                               const float* __restrict__ bias) {
    __shared__ float As[BK][BM + 4];
    __shared__ float Bs[BK][BN];
    const int tid = threadIdx.x;
    const int tx = tid & 15, ty = tid >> 4;
    const int n0 = blockIdx.x * BN;
    const int a0 = blockIdx.y * BM;

    float acc[8][8] = {};
    for (int k0 = 0; k0 < EMBED; k0 += BK) {
        {   // A tile: feat = inst + anchor, scatter transposed into As[k][m]
            int row = tid >> 1;
            int k4  = (tid & 1) * 4;
            float4 v = make_float4(0.f, 0.f, 0.f, 0.f);
            int ga = a0 + row;
            if (ga < NA) {
                float4 i4 = *(const float4*)(inst + ga * EMBED + k0 + k4);
                float4 a4 = *(const float4*)(anch + ga * EMBED + k0 + k4);
                v = make_float4(i4.x + a4.x, i4.y + a4.y, i4.z + a4.z, i4.w + a4.w);
            }
            As[k4 + 0][row] = v.x;
            As[k4 + 1][row] = v.y;
            As[k4 + 2][row] = v.z;
            As[k4 + 3][row] = v.w;
        }
        {   // B tile
            int brow = tid >> 5;
            int bc   = (tid & 31) * 4;
            float4 v = make_float4(0.f, 0.f, 0.f, 0.f);
            if (n0 + bc < NW)
                v = *(const float4*)(W + (k0 + brow) * NW + n0 + bc);
            *(float4*)&Bs[brow][bc] = v;
        }
        __syncthreads();
        #pragma unroll
        for (int kk = 0; kk < BK; kk++) {
            float rm[8], rn[8];
            *(float4*)&rm[0] = *(float4*)&As[kk][ty * 8];
            *(float4*)&rm[4] = *(float4*)&As[kk][ty * 8 + 4];
            *(float4*)&rn[0] = *(float4*)&Bs[kk][tx * 8];
            *(float4*)&rn[4] = *(float4*)&Bs[kk][tx * 8 + 4];
            #pragma unroll
            for (int i = 0; i < 8; i++)
                #pragma unroll
                for (int j = 0; j < 8; j++)
                    acc[i][j] += rm[i] * rn[j];
        }
        __syncthreads();
    }
    #pragma unroll
    for (int i = 0; i < 8; i++) {
        int a = a0 + ty * 8 + i;
        if (a >= NA) continue;
        #pragma unroll
        for (int j = 0; j < 8; j++) {
            int n = n0 + tx * 8 + j;
            if (n < NW) g_logits[a * NW + n] = acc[i][j] + bias[n];
        }
    }
}

// ---------------- 3) fused uv + softmax + sampling -------------------------
// 1 block = 1 anchor, 256 threads: lane = channel quad (64), tg = tap group (4).
__global__ __launch_bounds__(256) void k_sample(const float* __restrict__ kp,
                                                const float* __restrict__ proj,
                                                const float* __restrict__ wh) {
    __shared__ float  s_w[NW];                 // logits -> softmaxed weights
    __shared__ float2 s_uv[NCAM * NPTS];
    __shared__ float4 s_red[256];
    const int a = blockIdx.x;
    const int tid = threadIdx.x;

    // stage logits (coalesced float4)
    {
        const float4* L4 = (const float4*)(g_logits + a * NW);
        float4* S4 = (float4*)s_w;
        for (int t = tid; t < NW / 4; t += 256) S4[t] = L4[t];
    }
    // project key points (threads 0..77)
    if (tid < NCAM * NPTS) {
        int c = tid / NPTS, p = tid % NPTS;
        const float* k3 = kp + (a * NPTS + p) * 3;
        float x = k3[0], y = k3[1], z = k3[2];
        const float* M = proj + c * 16;
        float px = M[0]*x + M[1]*y + M[2]*z  + M[3];
        float py = M[4]*x + M[5]*y + M[6]*z  + M[7];
        float pd = fmaxf(M[8]*x + M[9]*y + M[10]*z + M[11], 1e-5f);
        float u = (px / pd) / wh[c*2+0] * 2.f - 1.f;
        float v = (py / pd) / wh[c*2+1] * 2.f - 1.f;
        s_uv[tid] = make_float2(u, v);
    }
    __syncthreads();

    // softmax: warp w = group w, over 312 entries (stride-8 layout)
    {
        const int g = tid >> 5, lane = tid & 31;
        float mx = -1e30f;
        for (int j = lane; j < NJ; j += 32) mx = fmaxf(mx, s_w[j * NG + g]);
        #pragma unroll
        for (int o = 16; o; o >>= 1) mx = fmaxf(mx, __shfl_xor_sync(0xffffffffu, mx, o));
        float sum = 0.f;
        float vals[10];
        int cnt = 0;
        for (int j = lane; j < NJ; j += 32) {
            float e = __expf(s_w[j * NG + g] - mx);
            vals[cnt++] = e;
            sum += e;
        }
        #pragma unroll
        for (int o = 16; o; o >>= 1) sum += __shfl_xor_sync(0xffffffffu, sum, o);
        float inv = 1.f / sum;
        cnt = 0;
        for (int j = lane; j < NJ; j += 32) s_w[j * NG + g] = vals[cnt++] * inv;
    }
    __syncthreads();

    // sampling
    const int lane = tid & 63;
    const int tg   = tid >> 6;
    const int ch   = lane * 4;
    const int g    = ch >> 5;
    const int Wl[4]   = {176, 88, 44, 22};
    const int Hl[4]   = {64, 32, 16, 8};
    const int HWl[4]  = {HW0, HW1, HW2, HW3};
    const int LOFF[4] = {LOFF0, LOFF1, LOFF2, LOFF3};

    float acc0 = 0.f, acc1 = 0.f, acc2 = 0.f, acc3 = 0.f;
    for (int j = tg; j < NCAM * NPTS; j += 4) {
        const int c = j / NPTS, p = j % NPTS;
        float2 uv = s_uv[j];
        #pragma unroll
        for (int l = 0; l < NLVL; l++) {
            float gx = (uv.x + 1.f) * (Wl[l] * 0.5f) - 0.5f;
            float gy = (uv.y + 1.f) * (Hl[l] * 0.5f) - 0.5f;
            float x0f = floorf(gx), y0f = floorf(gy);
            float wx1 = gx - x0f,  wy1 = gy - y0f;
            float wx0 = 1.f - wx1, wy0 = 1.f - wy1;
            int x0 = (int)x0f, y0 = (int)y0f;
            bool vx0 = (x0f >= 0.f)       && (x0f <= (float)(Wl[l] - 1));
            bool vx1 = (x0f + 1.f >= 0.f) && (x0f + 1.f <= (float)(Wl[l] - 1));
            bool vy0 = (y0f >= 0.f)       && (y0f <= (float)(Hl[l] - 1));
            bool vy1 = (y0f + 1.f >= 0.f) && (y0f + 1.f <= (float)(Hl[l] - 1));

            const __nv_bfloat16* base =
                g_fmT + (size_t)(LOFF[l] + c * HWl[l]) * EMBED + ch;
            const int rs = Wl[l] * EMBED;
            uint2 q00 = {0u,0u}, q01 = {0u,0u}, q10 = {0u,0u}, q11 = {0u,0u};
            if (vy0) {
                const __nv_bfloat16* r0 = base + y0 * rs;
                if (vx0) q00 = __ldg((const uint2*)(r0 + x0 * EMBED));
                if (vx1) q01 = __ldg((const uint2*)(r0 + (x0 + 1) * EMBED));
            }
            if (vy1) {
                const __nv_bfloat16* r1 = base + (y0 + 1) * rs;
                if (vx0) q10 = __ldg((const uint2*)(r1 + x0 * EMBED));
                if (vx1) q11 = __ldg((const uint2*)(r1 + (x0 + 1) * EMBED));
            }
            float w = s_w[((c * NLVL + l) * NPTS + p) * NG + g];
            float w00 = wx0 * wy0 * w, w01 = wx1 * wy0 * w;
            float w10 = wx0 * wy1 * w, w11 = wx1 * wy1 * w;

            float2 a00 = __bfloat1622float2(*(__nv_bfloat162*)&q00.x);
            float2 b00 = __bfloat1622float2(*(__nv_bfloat162*)&q00.y);
            float2 a01 = __bfloat1622float2(*(__nv_bfloat162*)&q01.x);
            float2 b01 = __bfloat1622float2(*(__nv_bfloat162*)&q01.y);
            float2 a10 = __bfloat1622float2(*(__nv_bfloat162*)&q10.x);
            float2 b10 = __bfloat1622float2(*(__nv_bfloat162*)&q10.y);
            float2 a11 = __bfloat1622float2(*(__nv_bfloat162*)&q11.x);
            float2 b11 = __bfloat1622float2(*(__nv_bfloat162*)&q11.y);

            acc0 += w00 * a00.x + w01 * a01.x + w10 * a10.x + w11 * a11.x;
            acc1 += w00 * a00.y + w01 * a01.y + w10 * a10.y + w11 * a11.y;
            acc2 += w00 * b00.x + w01 * b01.x + w10 * b10.x + w11 * b11.x;
            acc3 += w00 * b00.y + w01 * b01.y + w10 * b10.y + w11 * b11.y;
        }
    }
    s_red[tid] = make_float4(acc0, acc1, acc2, acc3);
    __syncthreads();
    if (tid < 64) {
        float4 r0 = s_red[tid], r1 = s_red[tid + 64],
               r2 = s_red[tid + 128], r3 = s_red[tid + 192];
        float4 r = make_float4(r0.x + r1.x + r2.x + r3.x,
                               r0.y + r1.y + r2.y + r3.y,
                               r0.z + r1.z + r2.z + r3.z,
                               r0.w + r1.w + r2.w + r3.w);
        *(float4*)(g_fused + a * EMBED + tid * 4) = r;
    }
}

// ---------------- 4) output proj + bias + residual -------------------------
#define FBM 6
__global__ __launch_bounds__(256) void k_final(const float* __restrict__ inst,
                                               const float* __restrict__ Wout,
                                               const float* __restrict__ bout,
                                               float* __restrict__ out) {
    __shared__ float s_f[FBM][EMBED];
    const int a0 = blockIdx.x * FBM;
    const int tid = threadIdx.x;
    for (int i = tid; i < FBM * EMBED; i += 256)
        s_f[i / EMBED][i % EMBED] = g_fused[(a0 + i / EMBED) * EMBED + (i % EMBED)];
    __syncthreads();

    float acc[FBM] = {};
    const int j = tid;
    #pragma unroll 4
    for (int k = 0; k < EMBED; k++) {
        float wv = Wout[k * EMBED + j];
        #pragma unroll
        for (int r = 0; r < FBM; r++) acc[r] += s_f[r][k] * wv;
    }
    #pragma unroll
    for (int r = 0; r < FBM; r++) {
        int a = a0 + r;
        out[a * EMBED + j] = acc[r] + bout[j] + inst[a * EMBED + j];
    }
}

// ---------------- launch ---------------------------------------------------
extern "C" void kernel_launch(void* const* d_in, const int* in_sizes, int n_in,
                              void* d_out, int out_size) {
    const float* inst = (const float*)d_in[0];
    const float* anch = (const float*)d_in[1];
    const float* kp   = (const float*)d_in[2];
    const float* fm0  = (const float*)d_in[3];
    const float* fm1  = (const float*)d_in[4];
    const float* fm2  = (const float*)d_in[5];
    const float* fm3  = (const float*)d_in[6];
    const float* proj = (const float*)d_in[7];
    const float* wh   = (const float*)d_in[8];
    const float* Ww   = (const float*)d_in[9];
    const float* bw   = (const float*)d_in[10];
    const float* Wo   = (const float*)d_in[11];
    const float* bo   = (const float*)d_in[12];
    float* out = (float*)d_out;

    k_transpose<<<dim3(PBTOT, 4, NCAM), dim3(32, 32)>>>(fm0, fm1, fm2, fm3);
    k_gemm1<<<dim3((NW + BN - 1) / BN, (NA + BM - 1) / BM), 256>>>(inst, anch, Ww, bw);
    k_sample<<<NA, 256>>>(kp, proj, wh);
    k_final<<<NA / FBM, 256>>>(inst, Wo, bo, out);
}

// round 4
// speedup vs baseline: 1.8720x; 1.2320x over previous
#include <cuda_runtime.h>
#include <cuda_bf16.h>
#include <mma.h>
using namespace nvcuda;

#define NA    900
#define EMBED 256
#define NG    8
#define NCAM  6
#define NLVL  4
#define NPTS  13
#define NJ    312
#define NW    2496

#define HW0 11264
#define HW1 2816
#define HW2 704
#define HW3 176
#define LOFF0 0
#define LOFF1 67584
#define LOFF2 84480
#define LOFF3 88704
#define TOTPX 89760
#define FMT_ELEMS (TOTPX * EMBED)

#define PB0 352
#define PB1 88
#define PB2 22
#define PB3 6
#define PBTOT 468

// ---------------- scratch ----------------
__device__ __nv_bfloat16 g_fmT[FMT_ELEMS];
__device__ float g_logits[NA * NW];
__device__ float g_fused[NA * EMBED];

// ---------------- 1) fused transpose -----------------------------
__global__ void k_transpose(const float* __restrict__ fm0,
                            const float* __restrict__ fm1,
                            const float* __restrict__ fm2,
                            const float* __restrict__ fm3) {
    __shared__ float tile[32][65];
    int bx = blockIdx.x;
    const float* fm;
    int HW, loff;
    if (bx < PB0)                  { fm = fm0; HW = HW0; loff = LOFF0; }
    else if (bx < PB0 + PB1)       { fm = fm1; HW = HW1; loff = LOFF1; bx -= PB0; }
    else if (bx < PB0 + PB1 + PB2) { fm = fm2; HW = HW2; loff = LOFF2; bx -= PB0 + PB1; }
    else                           { fm = fm3; HW = HW3; loff = LOFF3; bx -= PB0 + PB1 + PB2; }

    const int c   = blockIdx.z;
    const int ch0 = blockIdx.y * 64;
    const int px0 = bx * 32;
    const int tx = threadIdx.x, ty = threadIdx.y;

    int px = px0 + tx;
    if (px < HW) {
        tile[tx][ty]      = fm[(c * EMBED + ch0 + ty) * HW + px];
        tile[tx][ty + 32] = fm[(c * EMBED + ch0 + ty + 32) * HW + px];
    }
    __syncthreads();
    int pw = px0 + ty;
    if (pw < HW) {
        __nv_bfloat162 v = __floats2bfloat162_rn(tile[ty][2 * tx],
                                                 tile[ty][2 * tx + 1]);
        *(__nv_bfloat162*)(g_fmT + (size_t)(loff + c * HW + pw) * EMBED
                           + ch0 + 2 * tx) = v;
    }
}

// ---------------- 2) weight GEMM: tf32 WMMA, 64x64 tiles -------------------
#define GBM 64
#define GBN 64
#define GKB 32
#define ALDA (GKB + 8)     // 40, multiple of 8
__global__ __launch_bounds__(256) void k_gemm_tc(const float* __restrict__ inst,
                                                 const float* __restrict__ anch,
                                                 const float* __restrict__ W,
                                                 const float* __restrict__ bias) {
    __shared__ float As[GBM][ALDA];
    __shared__ float Bs[GKB][GBN];
    __shared__ float Cs[GBM][GBN];

    const int tid  = threadIdx.x;
    const int warp = tid >> 5;
    const int wm   = warp >> 1;      // 0..3: 16-row band
    const int wn   = warp & 1;       // 0..1: 32-col band
    const int n0   = blockIdx.x * GBN;
    const int a0   = blockIdx.y * GBM;

    wmma::fragment<wmma::accumulator, 16, 16, 8, float> c0, c1;
    wmma::fill_fragment(c0, 0.0f);
    wmma::fill_fragment(c1, 0.0f);

    for (int k0 = 0; k0 < EMBED; k0 += GKB) {
        // A tile: 64 rows x 32 k (feat = inst + anchor)
        for (int t = tid; t < GBM * GKB / 4; t += 256) {
            int m  = t >> 3;              // 8 float4 per row
            int kc = (t & 7) * 4;
            float4 v = make_float4(0.f, 0.f, 0.f, 0.f);
            int ga = a0 + m;
            if (ga < NA) {
                float4 i4 = *(const float4*)(inst + ga * EMBED + k0 + kc);
                float4 a4 = *(const float4*)(anch + ga * EMBED + k0 + kc);
                v = make_float4(i4.x + a4.x, i4.y + a4.y, i4.z + a4.z, i4.w + a4.w);
            }
            *(float4*)&As[m][kc] = v;
        }
        // B tile: 32 k x 64 n  (NW = 39*64 exactly -> no n guard)
        for (int t = tid; t < GKB * GBN / 4; t += 256) {
            int kr = t >> 4;              // 16 float4 per row
            int nc = (t & 15) * 4;
            *(float4*)&Bs[kr][nc] = *(const float4*)(W + (k0 + kr) * NW + n0 + nc);
        }
        __syncthreads();
        #pragma unroll
        for (int kk = 0; kk < GKB; kk += 8) {
            wmma::fragment<wmma::matrix_a, 16, 16, 8, wmma::precision::tf32, wmma::row_major> af;
            wmma::fragment<wmma::matrix_b, 16, 16, 8, wmma::precision::tf32, wmma::row_major> bf0, bf1;
            wmma::load_matrix_sync(af, &As[wm * 16][kk], ALDA);
            wmma::load_matrix_sync(bf0, &Bs[kk][wn * 32], GBN);
            wmma::load_matrix_sync(bf1, &Bs[kk][wn * 32 + 16], GBN);
            #pragma unroll
            for (int i = 0; i < af.num_elements; i++)
                af.x[i] = wmma::__float_to_tf32(af.x[i]);
            #pragma unroll
            for (int i = 0; i < bf0.num_elements; i++) {
                bf0.x[i] = wmma::__float_to_tf32(bf0.x[i]);
                bf1.x[i] = wmma::__float_to_tf32(bf1.x[i]);
            }
            wmma::mma_sync(c0, af, bf0, c0);
            wmma::mma_sync(c1, af, bf1, c1);
        }
        __syncthreads();
    }
    wmma::store_matrix_sync(&Cs[wm * 16][wn * 32], c0, GBN, wmma::mem_row_major);
    wmma::store_matrix_sync(&Cs[wm * 16][wn * 32 + 16], c1, GBN, wmma::mem_row_major);
    __syncthreads();
    for (int t = tid; t < GBM * GBN / 4; t += 256) {
        int m  = t >> 4;
        int nc = (t & 15) * 4;
        int ga = a0 + m;
        if (ga >= NA) continue;
        float4 v = *(float4*)&Cs[m][nc];
        float4 bb = *(const float4*)(bias + n0 + nc);
        v.x += bb.x; v.y += bb.y; v.z += bb.z; v.w += bb.w;
        *(float4*)(g_logits + ga * NW + n0 + nc) = v;
    }
}

// ---------------- 3) fused uv + softmax + sampling -------------------------
__global__ __launch_bounds__(256) void k_sample(const float* __restrict__ kp,
                                                const float* __restrict__ proj,
                                                const float* __restrict__ wh) {
    __shared__ float  s_w[NW];
    __shared__ float2 s_uv[NCAM * NPTS];
    __shared__ float4 s_red[256];
    const int a = blockIdx.x;
    const int tid = threadIdx.x;

    {
        const float4* L4 = (const float4*)(g_logits + a * NW);
        float4* S4 = (float4*)s_w;
        for (int t = tid; t < NW / 4; t += 256) S4[t] = L4[t];
    }
    if (tid < NCAM * NPTS) {
        int c = tid / NPTS, p = tid % NPTS;
        const float* k3 = kp + (a * NPTS + p) * 3;
        float x = k3[0], y = k3[1], z = k3[2];
        const float* M = proj + c * 16;
        float px = M[0]*x + M[1]*y + M[2]*z  + M[3];
        float py = M[4]*x + M[5]*y + M[6]*z  + M[7];
        float pd = fmaxf(M[8]*x + M[9]*y + M[10]*z + M[11], 1e-5f);
        float u = (px / pd) / wh[c*2+0] * 2.f - 1.f;
        float v = (py / pd) / wh[c*2+1] * 2.f - 1.f;
        s_uv[tid] = make_float2(u, v);
    }
    __syncthreads();

    {
        const int g = tid >> 5, lane = tid & 31;
        float mx = -1e30f;
        for (int j = lane; j < NJ; j += 32) mx = fmaxf(mx, s_w[j * NG + g]);
        #pragma unroll
        for (int o = 16; o; o >>= 1) mx = fmaxf(mx, __shfl_xor_sync(0xffffffffu, mx, o));
        float sum = 0.f;
        float vals[10];
        int cnt = 0;
        for (int j = lane; j < NJ; j += 32) {
            float e = __expf(s_w[j * NG + g] - mx);
            vals[cnt++] = e;
            sum += e;
        }
        #pragma unroll
        for (int o = 16; o; o >>= 1) sum += __shfl_xor_sync(0xffffffffu, sum, o);
        float inv = 1.f / sum;
        cnt = 0;
        for (int j = lane; j < NJ; j += 32) s_w[j * NG + g] = vals[cnt++] * inv;
    }
    __syncthreads();

    const int lane = tid & 63;
    const int tg   = tid >> 6;
    const int ch   = lane * 4;
    const int g    = ch >> 5;
    const int Wl[4]   = {176, 88, 44, 22};
    const int Hl[4]   = {64, 32, 16, 8};
    const int HWl[4]  = {HW0, HW1, HW2, HW3};
    const int LOFF[4] = {LOFF0, LOFF1, LOFF2, LOFF3};

    float acc0 = 0.f, acc1 = 0.f, acc2 = 0.f, acc3 = 0.f;
    for (int j = tg; j < NCAM * NPTS; j += 4) {
        const int c = j / NPTS, p = j % NPTS;
        float2 uv = s_uv[j];
        #pragma unroll
        for (int l = 0; l < NLVL; l++) {
            float gx = (uv.x + 1.f) * (Wl[l] * 0.5f) - 0.5f;
            float gy = (uv.y + 1.f) * (Hl[l] * 0.5f) - 0.5f;
            float x0f = floorf(gx), y0f = floorf(gy);
            float wx1 = gx - x0f,  wy1 = gy - y0f;
            float wx0 = 1.f - wx1, wy0 = 1.f - wy1;
            int x0 = (int)x0f, y0 = (int)y0f;
            bool vx0 = (x0f >= 0.f)       && (x0f <= (float)(Wl[l] - 1));
            bool vx1 = (x0f + 1.f >= 0.f) && (x0f + 1.f <= (float)(Wl[l] - 1));
            bool vy0 = (y0f >= 0.f)       && (y0f <= (float)(Hl[l] - 1));
            bool vy1 = (y0f + 1.f >= 0.f) && (y0f + 1.f <= (float)(Hl[l] - 1));

            const __nv_bfloat16* base =
                g_fmT + (size_t)(LOFF[l] + c * HWl[l]) * EMBED + ch;
            const int rs = Wl[l] * EMBED;
            uint2 q00 = {0u,0u}, q01 = {0u,0u}, q10 = {0u,0u}, q11 = {0u,0u};
            if (vy0) {
                const __nv_bfloat16* r0 = base + y0 * rs;
                if (vx0) q00 = __ldg((const uint2*)(r0 + x0 * EMBED));
                if (vx1) q01 = __ldg((const uint2*)(r0 + (x0 + 1) * EMBED));
            }
            if (vy1) {
                const __nv_bfloat16* r1 = base + (y0 + 1) * rs;
                if (vx0) q10 = __ldg((const uint2*)(r1 + x0 * EMBED));
                if (vx1) q11 = __ldg((const uint2*)(r1 + (x0 + 1) * EMBED));
            }
            float w = s_w[((c * NLVL + l) * NPTS + p) * NG + g];
            float w00 = wx0 * wy0 * w, w01 = wx1 * wy0 * w;
            float w10 = wx0 * wy1 * w, w11 = wx1 * wy1 * w;

            float2 a00 = __bfloat1622float2(*(__nv_bfloat162*)&q00.x);
            float2 b00 = __bfloat1622float2(*(__nv_bfloat162*)&q00.y);
            float2 a01 = __bfloat1622float2(*(__nv_bfloat162*)&q01.x);
            float2 b01 = __bfloat1622float2(*(__nv_bfloat162*)&q01.y);
            float2 a10 = __bfloat1622float2(*(__nv_bfloat162*)&q10.x);
            float2 b10 = __bfloat1622float2(*(__nv_bfloat162*)&q10.y);
            float2 a11 = __bfloat1622float2(*(__nv_bfloat162*)&q11.x);
            float2 b11 = __bfloat1622float2(*(__nv_bfloat162*)&q11.y);

            acc0 += w00 * a00.x + w01 * a01.x + w10 * a10.x + w11 * a11.x;
            acc1 += w00 * a00.y + w01 * a01.y + w10 * a10.y + w11 * a11.y;
            acc2 += w00 * b00.x + w01 * b01.x + w10 * b10.x + w11 * b11.x;
            acc3 += w00 * b00.y + w01 * b01.y + w10 * b10.y + w11 * b11.y;
        }
    }
    s_red[tid] = make_float4(acc0, acc1, acc2, acc3);
    __syncthreads();
    if (tid < 64) {
        float4 r0 = s_red[tid], r1 = s_red[tid + 64],
               r2 = s_red[tid + 128], r3 = s_red[tid + 192];
        float4 r = make_float4(r0.x + r1.x + r2.x + r3.x,
                               r0.y + r1.y + r2.y + r3.y,
                               r0.z + r1.z + r2.z + r3.z,
                               r0.w + r1.w + r2.w + r3.w);
        *(float4*)(g_fused + a * EMBED + tid * 4) = r;
    }
}

// ---------------- 4) output proj: k-split, float4, 300 blocks --------------
#define FBM 3
__global__ __launch_bounds__(256) void k_final(const float* __restrict__ inst,
                                               const float* __restrict__ Wout,
                                               const float* __restrict__ bout,
                                               float* __restrict__ out) {
    __shared__ float  s_f[FBM][EMBED];
    __shared__ float4 s_red[4][FBM][64];
    const int a0 = blockIdx.x * FBM;
    const int tid = threadIdx.x;
    for (int i = tid; i < FBM * EMBED; i += 256)
        s_f[i >> 8][i & 255] = g_fused[a0 * EMBED + i];
    __syncthreads();

    const int l  = tid & 63;
    const int kg = tid >> 6;
    const int j  = l * 4;
    float4 acc[FBM];
    #pragma unroll
    for (int r = 0; r < FBM; r++) acc[r] = make_float4(0.f, 0.f, 0.f, 0.f);

    const int kbeg = kg * 64;
    #pragma unroll 4
    for (int k = kbeg; k < kbeg + 64; k++) {
        float4 w4 = __ldg((const float4*)(Wout + k * EMBED + j));
        #pragma unroll
        for (int r = 0; r < FBM; r++) {
            float f = s_f[r][k];
            acc[r].x += f * w4.x; acc[r].y += f * w4.y;
            acc[r].z += f * w4.z; acc[r].w += f * w4.w;
        }
    }
    #pragma unroll
    for (int r = 0; r < FBM; r++) s_red[kg][r][l] = acc[r];
    __syncthreads();

    if (tid < FBM * 64) {
        int r = tid >> 6, ll = tid & 63, jj = ll * 4;
        float4 v0 = s_red[0][r][ll], v1 = s_red[1][r][ll],
               v2 = s_red[2][r][ll], v3 = s_red[3][r][ll];
        float4 v = make_float4(v0.x + v1.x + v2.x + v3.x,
                               v0.y + v1.y + v2.y + v3.y,
                               v0.z + v1.z + v2.z + v3.z,
                               v0.w + v1.w + v2.w + v3.w);
        int a = a0 + r;
        float4 bb = *(const float4*)(bout + jj);
        float4 ii = *(const float4*)(inst + a * EMBED + jj);
        v.x += bb.x + ii.x; v.y += bb.y + ii.y;
        v.z += bb.z + ii.z; v.w += bb.w + ii.w;
        *(float4*)(out + a * EMBED + jj) = v;
    }
}

// ---------------- launch ---------------------------------------------------
extern "C" void kernel_launch(void* const* d_in, const int* in_sizes, int n_in,
                              void* d_out, int out_size) {
    const float* inst = (const float*)d_in[0];
    const float* anch = (const float*)d_in[1];
    const float* kp   = (const float*)d_in[2];
    const float* fm0  = (const float*)d_in[3];
    const float* fm1  = (const float*)d_in[4];
    const float* fm2  = (const float*)d_in[5];
    const float* fm3  = (const float*)d_in[6];
    const float* proj = (const float*)d_in[7];
    const float* wh   = (const float*)d_in[8];
    const float* Ww   = (const float*)d_in[9];
    const float* bw   = (const float*)d_in[10];
    const float* Wo   = (const float*)d_in[11];
    const float* bo   = (const float*)d_in[12];
    float* out = (float*)d_out;

    k_transpose<<<dim3(PBTOT, 4, NCAM), dim3(32, 32)>>>(fm0, fm1, fm2, fm3);
    k_gemm_tc<<<dim3(NW / GBN, (NA + GBM - 1) / GBM), 256>>>(inst, anch, Ww, bw);
    k_sample<<<NA, 256>>>(kp, proj, wh);
    k_final<<<NA / FBM, 256>>>(inst, Wo, bo, out);
}

// round 5
// speedup vs baseline: 2.4649x; 1.3167x over previous
#include <cuda_runtime.h>
#include <cuda_bf16.h>
#include <mma.h>
using namespace nvcuda;

#define NA    900
#define EMBED 256
#define NG    8
#define NCAM  6
#define NLVL  4
#define NPTS  13
#define NJ    312
#define NW    2496

#define HW0 11264
#define HW1 2816
#define HW2 704
#define HW3 176
#define LOFF0 0
#define LOFF1 67584
#define LOFF2 84480
#define LOFF3 88704
#define TOTPX 89760
#define FMT_ELEMS (TOTPX * EMBED)

#define PB0 352
#define PB1 88
#define PB2 22
#define PB3 6
#define PBTOT 468

// ---------------- scratch ----------------
__device__ __nv_bfloat16 g_fmT[FMT_ELEMS];
__device__ float g_logits[NA * NW];
__device__ float g_fused[NA * EMBED];

// ---------------- 1) fused transpose: 32px x 64ch tiles, 256 threads -------
__global__ __launch_bounds__(256) void k_transpose(const float* __restrict__ fm0,
                                                   const float* __restrict__ fm1,
                                                   const float* __restrict__ fm2,
                                                   const float* __restrict__ fm3) {
    __shared__ float tile[32][65];   // [px][ch]
    int bx = blockIdx.x;
    const float* fm;
    int HW, loff;
    if (bx < PB0)                  { fm = fm0; HW = HW0; loff = LOFF0; }
    else if (bx < PB0 + PB1)       { fm = fm1; HW = HW1; loff = LOFF1; bx -= PB0; }
    else if (bx < PB0 + PB1 + PB2) { fm = fm2; HW = HW2; loff = LOFF2; bx -= PB0 + PB1; }
    else                           { fm = fm3; HW = HW3; loff = LOFF3; bx -= PB0 + PB1 + PB2; }

    const int c   = blockIdx.z;
    const int ch0 = blockIdx.y * 64;
    const int px0 = bx * 32;
    const int tx = threadIdx.x, ty = threadIdx.y;   // (32, 8)

    int px = px0 + tx;
    if (px < HW) {
        #pragma unroll
        for (int k = 0; k < 8; k++)
            tile[tx][ty + 8 * k] = fm[(c * EMBED + ch0 + ty + 8 * k) * HW + px];
    }
    __syncthreads();
    #pragma unroll
    for (int k = 0; k < 4; k++) {
        int r  = ty + 8 * k;                 // px row within tile
        int pw = px0 + r;
        if (pw < HW) {
            __nv_bfloat162 v = __floats2bfloat162_rn(tile[r][2 * tx],
                                                     tile[r][2 * tx + 1]);
            *(__nv_bfloat162*)(g_fmT + (size_t)(loff + c * HW + pw) * EMBED
                               + ch0 + 2 * tx) = v;
        }
    }
}

// ---------------- 2) weight GEMM: tf32 WMMA, 64x64 tiles -------------------
#define GBM 64
#define GBN 64
#define GKB 32
#define ALDA (GKB + 8)
__global__ __launch_bounds__(256) void k_gemm_tc(const float* __restrict__ inst,
                                                 const float* __restrict__ anch,
                                                 const float* __restrict__ W,
                                                 const float* __restrict__ bias) {
    __shared__ float As[GBM][ALDA];
    __shared__ float Bs[GKB][GBN];
    __shared__ float Cs[GBM][GBN];

    const int tid  = threadIdx.x;
    const int warp = tid >> 5;
    const int wm   = warp >> 1;
    const int wn   = warp & 1;
    const int n0   = blockIdx.x * GBN;
    const int a0   = blockIdx.y * GBM;

    wmma::fragment<wmma::accumulator, 16, 16, 8, float> c0, c1;
    wmma::fill_fragment(c0, 0.0f);
    wmma::fill_fragment(c1, 0.0f);

    for (int k0 = 0; k0 < EMBED; k0 += GKB) {
        for (int t = tid; t < GBM * GKB / 4; t += 256) {
            int m  = t >> 3;
            int kc = (t & 7) * 4;
            float4 v = make_float4(0.f, 0.f, 0.f, 0.f);
            int ga = a0 + m;
            if (ga < NA) {
                float4 i4 = *(const float4*)(inst + ga * EMBED + k0 + kc);
                float4 a4 = *(const float4*)(anch + ga * EMBED + k0 + kc);
                v = make_float4(i4.x + a4.x, i4.y + a4.y, i4.z + a4.z, i4.w + a4.w);
            }
            *(float4*)&As[m][kc] = v;
        }
        for (int t = tid; t < GKB * GBN / 4; t += 256) {
            int kr = t >> 4;
            int nc = (t & 15) * 4;
            *(float4*)&Bs[kr][nc] = *(const float4*)(W + (k0 + kr) * NW + n0 + nc);
        }
        __syncthreads();
        #pragma unroll
        for (int kk = 0; kk < GKB; kk += 8) {
            wmma::fragment<wmma::matrix_a, 16, 16, 8, wmma::precision::tf32, wmma::row_major> af;
            wmma::fragment<wmma::matrix_b, 16, 16, 8, wmma::precision::tf32, wmma::row_major> bf0, bf1;
            wmma::load_matrix_sync(af, &As[wm * 16][kk], ALDA);
            wmma::load_matrix_sync(bf0, &Bs[kk][wn * 32], GBN);
            wmma::load_matrix_sync(bf1, &Bs[kk][wn * 32 + 16], GBN);
            #pragma unroll
            for (int i = 0; i < af.num_elements; i++)
                af.x[i] = wmma::__float_to_tf32(af.x[i]);
            #pragma unroll
            for (int i = 0; i < bf0.num_elements; i++) {
                bf0.x[i] = wmma::__float_to_tf32(bf0.x[i]);
                bf1.x[i] = wmma::__float_to_tf32(bf1.x[i]);
            }
            wmma::mma_sync(c0, af, bf0, c0);
            wmma::mma_sync(c1, af, bf1, c1);
        }
        __syncthreads();
    }
    wmma::store_matrix_sync(&Cs[wm * 16][wn * 32], c0, GBN, wmma::mem_row_major);
    wmma::store_matrix_sync(&Cs[wm * 16][wn * 32 + 16], c1, GBN, wmma::mem_row_major);
    __syncthreads();
    for (int t = tid; t < GBM * GBN / 4; t += 256) {
        int m  = t >> 4;
        int nc = (t & 15) * 4;
        int ga = a0 + m;
        if (ga >= NA) continue;
        float4 v = *(float4*)&Cs[m][nc];
        float4 bb = *(const float4*)(bias + n0 + nc);
        v.x += bb.x; v.y += bb.y; v.z += bb.z; v.w += bb.w;
        *(float4*)(g_logits + ga * NW + n0 + nc) = v;
    }
}

// ---------------- 3) fused uv + softmax + precompute + streaming sample ----
__global__ __launch_bounds__(256) void k_sample(const float* __restrict__ kp,
                                                const float* __restrict__ proj,
                                                const float* __restrict__ wh) {
    __shared__ float  s_w[NW];               // logits -> softmax weights
    __shared__ float2 s_uv[NCAM * NPTS];
    __shared__ int    s_off[NJ][4];          // corner BYTE offsets (clamped)
    __shared__ uint2  s_cw[NJ][NG];          // packed bf16 combined weights
    __shared__ float4 s_red[256];
    const int a = blockIdx.x;
    const int tid = threadIdx.x;

    {   // stage logits
        const float4* L4 = (const float4*)(g_logits + a * NW);
        float4* S4 = (float4*)s_w;
        for (int t = tid; t < NW / 4; t += 256) S4[t] = L4[t];
    }
    if (tid < NCAM * NPTS) {   // project key points
        int c = tid / NPTS, p = tid % NPTS;
        const float* k3 = kp + (a * NPTS + p) * 3;
        float x = k3[0], y = k3[1], z = k3[2];
        const float* M = proj + c * 16;
        float px = M[0]*x + M[1]*y + M[2]*z  + M[3];
        float py = M[4]*x + M[5]*y + M[6]*z  + M[7];
        float pd = fmaxf(M[8]*x + M[9]*y + M[10]*z + M[11], 1e-5f);
        float u = (px / pd) / wh[c*2+0] * 2.f - 1.f;
        float v = (py / pd) / wh[c*2+1] * 2.f - 1.f;
        s_uv[tid] = make_float2(u, v);
    }
    __syncthreads();

    {   // softmax per group (warp = group)
        const int g = tid >> 5, lane = tid & 31;
        float mx = -1e30f;
        for (int j = lane; j < NJ; j += 32) mx = fmaxf(mx, s_w[j * NG + g]);
        #pragma unroll
        for (int o = 16; o; o >>= 1) mx = fmaxf(mx, __shfl_xor_sync(0xffffffffu, mx, o));
        float sum = 0.f;
        float vals[10];
        int cnt = 0;
        for (int j = lane; j < NJ; j += 32) {
            float e = __expf(s_w[j * NG + g] - mx);
            vals[cnt++] = e;
            sum += e;
        }
        #pragma unroll
        for (int o = 16; o; o >>= 1) sum += __shfl_xor_sync(0xffffffffu, sum, o);
        float inv = 1.f / sum;
        cnt = 0;
        for (int j = lane; j < NJ; j += 32) s_w[j * NG + g] = vals[cnt++] * inv;
    }
    __syncthreads();

    // per-tap geometry + combined weights
    for (int t = tid; t < NJ; t += 256) {
        int p  = t % NPTS;
        int cl = t / NPTS;
        int l  = cl & 3;
        int c  = cl >> 2;
        int Wl = 176 >> l, Hl = 64 >> l;
        int HWl  = 11264 >> (2 * l);
        int loff = (l >= 1 ? 67584 : 0) + (l >= 2 ? 16896 : 0) + (l >= 3 ? 4224 : 0);

        float2 uv = s_uv[c * NPTS + p];
        float gx = (uv.x + 1.f) * (Wl * 0.5f) - 0.5f;
        float gy = (uv.y + 1.f) * (Hl * 0.5f) - 0.5f;
        float x0f = floorf(gx), y0f = floorf(gy);
        float wx1 = gx - x0f,  wy1 = gy - y0f;
        float wx0 = 1.f - wx1, wy0 = 1.f - wy1;
        int x0 = (int)x0f, y0 = (int)y0f;
        bool vx0 = (x0 >= 0) && (x0 <= Wl - 1);
        bool vx1 = (x0 + 1 >= 0) && (x0 + 1 <= Wl - 1);
        bool vy0 = (y0 >= 0) && (y0 <= Hl - 1);
        bool vy1 = (y0 + 1 >= 0) && (y0 + 1 <= Hl - 1);
        int x0c = min(max(x0, 0), Wl - 1);
        int x1c = min(max(x0 + 1, 0), Wl - 1);
        int y0c = min(max(y0, 0), Hl - 1);
        int y1c = min(max(y0 + 1, 0), Hl - 1);

        int base = loff + c * HWl;
        s_off[t][0] = (base + y0c * Wl + x0c) * EMBED * 2;
        s_off[t][1] = (base + y0c * Wl + x1c) * EMBED * 2;
        s_off[t][2] = (base + y1c * Wl + x0c) * EMBED * 2;
        s_off[t][3] = (base + y1c * Wl + x1c) * EMBED * 2;

        float g00 = (vx0 && vy0) ? wx0 * wy0 : 0.f;
        float g01 = (vx1 && vy0) ? wx1 * wy0 : 0.f;
        float g10 = (vx0 && vy1) ? wx0 * wy1 : 0.f;
        float g11 = (vx1 && vy1) ? wx1 * wy1 : 0.f;

        #pragma unroll
        for (int g = 0; g < NG; g++) {
            float wg = s_w[t * NG + g];
            __nv_bfloat162 lo = __floats2bfloat162_rn(g00 * wg, g01 * wg);
            __nv_bfloat162 hi = __floats2bfloat162_rn(g10 * wg, g11 * wg);
            s_cw[t][g] = make_uint2(*(unsigned*)&lo, *(unsigned*)&hi);
        }
    }
    __syncthreads();

    // streaming main loop: lane = 4 channels, tg = tap quarter
    const int lane = tid & 63;
    const int tg   = tid >> 6;
    const int ch   = lane * 4;
    const int g    = ch >> 5;
    const char* fb = (const char*)g_fmT + ch * 2;

    float acc0 = 0.f, acc1 = 0.f, acc2 = 0.f, acc3 = 0.f;
    #pragma unroll 2
    for (int t = tg; t < NJ; t += 4) {
        int4 off = *(int4*)s_off[t];
        uint2 wp = s_cw[t][g];
        __nv_bfloat162 wlo = *(__nv_bfloat162*)&wp.x;
        __nv_bfloat162 whi = *(__nv_bfloat162*)&wp.y;
        __nv_bfloat162 w00 = __low2bfloat162(wlo);
        __nv_bfloat162 w01 = __high2bfloat162(wlo);
        __nv_bfloat162 w10 = __low2bfloat162(whi);
        __nv_bfloat162 w11 = __high2bfloat162(whi);

        uint2 q00 = __ldg((const uint2*)(fb + off.x));
        uint2 q01 = __ldg((const uint2*)(fb + off.y));
        uint2 q10 = __ldg((const uint2*)(fb + off.z));
        uint2 q11 = __ldg((const uint2*)(fb + off.w));

        __nv_bfloat162 bA = __hmul2(*(__nv_bfloat162*)&q00.x, w00);
        bA = __hfma2(*(__nv_bfloat162*)&q01.x, w01, bA);
        bA = __hfma2(*(__nv_bfloat162*)&q10.x, w10, bA);
        bA = __hfma2(*(__nv_bfloat162*)&q11.x, w11, bA);
        __nv_bfloat162 bB = __hmul2(*(__nv_bfloat162*)&q00.y, w00);
        bB = __hfma2(*(__nv_bfloat162*)&q01.y, w01, bB);
        bB = __hfma2(*(__nv_bfloat162*)&q10.y, w10, bB);
        bB = __hfma2(*(__nv_bfloat162*)&q11.y, w11, bB);

        float2 fA = __bfloat1622float2(bA);
        float2 fB = __bfloat1622float2(bB);
        acc0 += fA.x; acc1 += fA.y; acc2 += fB.x; acc3 += fB.y;
    }
    s_red[tid] = make_float4(acc0, acc1, acc2, acc3);
    __syncthreads();
    if (tid < 64) {
        float4 r0 = s_red[tid], r1 = s_red[tid + 64],
               r2 = s_red[tid + 128], r3 = s_red[tid + 192];
        float4 r = make_float4(r0.x + r1.x + r2.x + r3.x,
                               r0.y + r1.y + r2.y + r3.y,
                               r0.z + r1.z + r2.z + r3.z,
                               r0.w + r1.w + r2.w + r3.w);
        *(float4*)(g_fused + a * EMBED + tid * 4) = r;
    }
}

// ---------------- 4) output proj: tf32 WMMA + bias + residual --------------
__global__ __launch_bounds__(256) void k_final_tc(const float* __restrict__ inst,
                                                  const float* __restrict__ Wout,
                                                  const float* __restrict__ bout,
                                                  float* __restrict__ out) {
    __shared__ float As[GBM][ALDA];
    __shared__ float Bs[GKB][GBN];
    __shared__ float Cs[GBM][GBN];

    const int tid  = threadIdx.x;
    const int warp = tid >> 5;
    const int wm   = warp >> 1;
    const int wn   = warp & 1;
    const int n0   = blockIdx.x * GBN;
    const int a0   = blockIdx.y * GBM;

    wmma::fragment<wmma::accumulator, 16, 16, 8, float> c0, c1;
    wmma::fill_fragment(c0, 0.0f);
    wmma::fill_fragment(c1, 0.0f);

    for (int k0 = 0; k0 < EMBED; k0 += GKB) {
        for (int t = tid; t < GBM * GKB / 4; t += 256) {
            int m  = t >> 3;
            int kc = (t & 7) * 4;
            float4 v = make_float4(0.f, 0.f, 0.f, 0.f);
            int ga = a0 + m;
            if (ga < NA)
                v = *(const float4*)(g_fused + ga * EMBED + k0 + kc);
            *(float4*)&As[m][kc] = v;
        }
        for (int t = tid; t < GKB * GBN / 4; t += 256) {
            int kr = t >> 4;
            int nc = (t & 15) * 4;
            *(float4*)&Bs[kr][nc] = *(const float4*)(Wout + (k0 + kr) * EMBED + n0 + nc);
        }
        __syncthreads();
        #pragma unroll
        for (int kk = 0; kk < GKB; kk += 8) {
            wmma::fragment<wmma::matrix_a, 16, 16, 8, wmma::precision::tf32, wmma::row_major> af;
            wmma::fragment<wmma::matrix_b, 16, 16, 8, wmma::precision::tf32, wmma::row_major> bf0, bf1;
            wmma::load_matrix_sync(af, &As[wm * 16][kk], ALDA);
            wmma::load_matrix_sync(bf0, &Bs[kk][wn * 32], GBN);
            wmma::load_matrix_sync(bf1, &Bs[kk][wn * 32 + 16], GBN);
            #pragma unroll
            for (int i = 0; i < af.num_elements; i++)
                af.x[i] = wmma::__float_to_tf32(af.x[i]);
            #pragma unroll
            for (int i = 0; i < bf0.num_elements; i++) {
                bf0.x[i] = wmma::__float_to_tf32(bf0.x[i]);
                bf1.x[i] = wmma::__float_to_tf32(bf1.x[i]);
            }
            wmma::mma_sync(c0, af, bf0, c0);
            wmma::mma_sync(c1, af, bf1, c1);
        }
        __syncthreads();
    }
    wmma::store_matrix_sync(&Cs[wm * 16][wn * 32], c0, GBN, wmma::mem_row_major);
    wmma::store_matrix_sync(&Cs[wm * 16][wn * 32 + 16], c1, GBN, wmma::mem_row_major);
    __syncthreads();
    for (int t = tid; t < GBM * GBN / 4; t += 256) {
        int m  = t >> 4;
        int nc = (t & 15) * 4;
        int ga = a0 + m;
        if (ga >= NA) continue;
        float4 v  = *(float4*)&Cs[m][nc];
        float4 bb = *(const float4*)(bout + n0 + nc);
        float4 ii = *(const float4*)(inst + ga * EMBED + n0 + nc);
        v.x += bb.x + ii.x; v.y += bb.y + ii.y;
        v.z += bb.z + ii.z; v.w += bb.w + ii.w;
        *(float4*)(out + ga * EMBED + n0 + nc) = v;
    }
}

// ---------------- launch ---------------------------------------------------
extern "C" void kernel_launch(void* const* d_in, const int* in_sizes, int n_in,
                              void* d_out, int out_size) {
    const float* inst = (const float*)d_in[0];
    const float* anch = (const float*)d_in[1];
    const float* kp   = (const float*)d_in[2];
    const float* fm0  = (const float*)d_in[3];
    const float* fm1  = (const float*)d_in[4];
    const float* fm2  = (const float*)d_in[5];
    const float* fm3  = (const float*)d_in[6];
    const float* proj = (const float*)d_in[7];
    const float* wh   = (const float*)d_in[8];
    const float* Ww   = (const float*)d_in[9];
    const float* bw   = (const float*)d_in[10];
    const float* Wo   = (const float*)d_in[11];
    const float* bo   = (const float*)d_in[12];
    float* out = (float*)d_out;

    k_transpose<<<dim3(PBTOT, 4, NCAM), dim3(32, 8)>>>(fm0, fm1, fm2, fm3);
    k_gemm_tc<<<dim3(NW / GBN, (NA + GBM - 1) / GBM), 256>>>(inst, anch, Ww, bw);
    k_sample<<<NA, 256>>>(kp, proj, wh);
    k_final_tc<<<dim3(EMBED / GBN, (NA + GBM - 1) / GBM), 256>>>(inst, Wo, bo, out);
}

// round 6
// speedup vs baseline: 2.7520x; 1.1164x over previous
#include <cuda_runtime.h>
#include <cuda_bf16.h>
#include <mma.h>
using namespace nvcuda;

#define NA    900
#define EMBED 256
#define NG    8
#define NCAM  6
#define NLVL  4
#define NPTS  13
#define NJ    312
#define NW    2496

#define HW0 11264
#define HW1 2816
#define HW2 704
#define HW3 176
#define LOFF0 0
#define LOFF1 67584
#define LOFF2 84480
#define LOFF3 88704
#define TOTPX 89760
#define FMT_ELEMS (TOTPX * EMBED)

#define PB0 352
#define PB1 88
#define PB2 22
#define PB3 6
#define PBTOT 468

// ---------------- scratch ----------------
__device__ __nv_bfloat16 g_fmT[FMT_ELEMS];
__device__ float g_logits[NA * NW];
__device__ __nv_bfloat16 g_WoutB[EMBED * EMBED];

// ---------------- 1) fused transpose ---------------------------------------
__global__ __launch_bounds__(256) void k_transpose(const float* __restrict__ fm0,
                                                   const float* __restrict__ fm1,
                                                   const float* __restrict__ fm2,
                                                   const float* __restrict__ fm3) {
    __shared__ float tile[32][65];
    int bx = blockIdx.x;
    const float* fm;
    int HW, loff;
    if (bx < PB0)                  { fm = fm0; HW = HW0; loff = LOFF0; }
    else if (bx < PB0 + PB1)       { fm = fm1; HW = HW1; loff = LOFF1; bx -= PB0; }
    else if (bx < PB0 + PB1 + PB2) { fm = fm2; HW = HW2; loff = LOFF2; bx -= PB0 + PB1; }
    else                           { fm = fm3; HW = HW3; loff = LOFF3; bx -= PB0 + PB1 + PB2; }

    const int c   = blockIdx.z;
    const int ch0 = blockIdx.y * 64;
    const int px0 = bx * 32;
    const int tx = threadIdx.x, ty = threadIdx.y;   // (32, 8)

    int px = px0 + tx;
    if (px < HW) {
        #pragma unroll
        for (int k = 0; k < 8; k++)
            tile[tx][ty + 8 * k] = fm[(c * EMBED + ch0 + ty + 8 * k) * HW + px];
    }
    __syncthreads();
    #pragma unroll
    for (int k = 0; k < 4; k++) {
        int r  = ty + 8 * k;
        int pw = px0 + r;
        if (pw < HW) {
            __nv_bfloat162 v = __floats2bfloat162_rn(tile[r][2 * tx],
                                                     tile[r][2 * tx + 1]);
            *(__nv_bfloat162*)(g_fmT + (size_t)(loff + c * HW + pw) * EMBED
                               + ch0 + 2 * tx) = v;
        }
    }
}

// ---------------- 1b) Wout -> bf16 -----------------------------------------
__global__ __launch_bounds__(256) void k_wcvt(const float* __restrict__ Wout) {
    int t = (blockIdx.x * 256 + threadIdx.x) * 4;
    float4 v = *(const float4*)(Wout + t);
    __nv_bfloat162 lo = __floats2bfloat162_rn(v.x, v.y);
    __nv_bfloat162 hi = __floats2bfloat162_rn(v.z, v.w);
    *(uint2*)(g_WoutB + t) = make_uint2(*(unsigned*)&lo, *(unsigned*)&hi);
}

// ---------------- 2) weight GEMM: tf32 WMMA --------------------------------
#define GBM 64
#define GBN 64
#define GKB 32
#define ALDA (GKB + 8)
__global__ __launch_bounds__(256) void k_gemm_tc(const float* __restrict__ inst,
                                                 const float* __restrict__ anch,
                                                 const float* __restrict__ W,
                                                 const float* __restrict__ bias) {
    __shared__ float As[GBM][ALDA];
    __shared__ float Bs[GKB][GBN];
    __shared__ float Cs[GBM][GBN];

    const int tid  = threadIdx.x;
    const int warp = tid >> 5;
    const int wm   = warp >> 1;
    const int wn   = warp & 1;
    const int n0   = blockIdx.x * GBN;
    const int a0   = blockIdx.y * GBM;

    wmma::fragment<wmma::accumulator, 16, 16, 8, float> c0, c1;
    wmma::fill_fragment(c0, 0.0f);
    wmma::fill_fragment(c1, 0.0f);

    for (int k0 = 0; k0 < EMBED; k0 += GKB) {
        for (int t = tid; t < GBM * GKB / 4; t += 256) {
            int m  = t >> 3;
            int kc = (t & 7) * 4;
            float4 v = make_float4(0.f, 0.f, 0.f, 0.f);
            int ga = a0 + m;
            if (ga < NA) {
                float4 i4 = *(const float4*)(inst + ga * EMBED + k0 + kc);
                float4 a4 = *(const float4*)(anch + ga * EMBED + k0 + kc);
                v = make_float4(i4.x + a4.x, i4.y + a4.y, i4.z + a4.z, i4.w + a4.w);
            }
            *(float4*)&As[m][kc] = v;
        }
        for (int t = tid; t < GKB * GBN / 4; t += 256) {
            int kr = t >> 4;
            int nc = (t & 15) * 4;
            *(float4*)&Bs[kr][nc] = *(const float4*)(W + (k0 + kr) * NW + n0 + nc);
        }
        __syncthreads();
        #pragma unroll
        for (int kk = 0; kk < GKB; kk += 8) {
            wmma::fragment<wmma::matrix_a, 16, 16, 8, wmma::precision::tf32, wmma::row_major> af;
            wmma::fragment<wmma::matrix_b, 16, 16, 8, wmma::precision::tf32, wmma::row_major> bf0, bf1;
            wmma::load_matrix_sync(af, &As[wm * 16][kk], ALDA);
            wmma::load_matrix_sync(bf0, &Bs[kk][wn * 32], GBN);
            wmma::load_matrix_sync(bf1, &Bs[kk][wn * 32 + 16], GBN);
            #pragma unroll
            for (int i = 0; i < af.num_elements; i++)
                af.x[i] = wmma::__float_to_tf32(af.x[i]);
            #pragma unroll
            for (int i = 0; i < bf0.num_elements; i++) {
                bf0.x[i] = wmma::__float_to_tf32(bf0.x[i]);
                bf1.x[i] = wmma::__float_to_tf32(bf1.x[i]);
            }
            wmma::mma_sync(c0, af, bf0, c0);
            wmma::mma_sync(c1, af, bf1, c1);
        }
        __syncthreads();
    }
    wmma::store_matrix_sync(&Cs[wm * 16][wn * 32], c0, GBN, wmma::mem_row_major);
    wmma::store_matrix_sync(&Cs[wm * 16][wn * 32 + 16], c1, GBN, wmma::mem_row_major);
    __syncthreads();
    for (int t = tid; t < GBM * GBN / 4; t += 256) {
        int m  = t >> 4;
        int nc = (t & 15) * 4;
        int ga = a0 + m;
        if (ga >= NA) continue;
        float4 v = *(float4*)&Cs[m][nc];
        float4 bb = *(const float4*)(bias + n0 + nc);
        v.x += bb.x; v.y += bb.y; v.z += bb.z; v.w += bb.w;
        *(float4*)(g_logits + ga * NW + n0 + nc) = v;
    }
}

// ---------------- 3) fused uv + softmax + compacted sampling + GEMV --------
#define B2(u) (*(__nv_bfloat162*)&(u))
__global__ __launch_bounds__(256) void k_sample(const float* __restrict__ kp,
                                                const float* __restrict__ proj,
                                                const float* __restrict__ wh,
                                                const float* __restrict__ inst,
                                                const float* __restrict__ bout,
                                                float* __restrict__ out) {
    __shared__ float  s_w[NW];
    __shared__ float2 s_uv[NCAM * NPTS];
    __shared__ int4   s_off[NJ];             // compacted corner byte-offsets
    __shared__ uint2  s_cw[NJ][NG];          // compacted packed bf16 weights
    __shared__ float  s_part[8][EMBED];      // cross-group reduction
    __shared__ float  s_f[EMBED];
    __shared__ int    s_nv;
    const int a = blockIdx.x;
    const int tid = threadIdx.x;

    if (tid == 0) s_nv = 0;
    {   // stage logits
        const float4* L4 = (const float4*)(g_logits + a * NW);
        float4* S4 = (float4*)s_w;
        for (int t = tid; t < NW / 4; t += 256) S4[t] = L4[t];
    }
    if (tid < NCAM * NPTS) {   // project key points
        int c = tid / NPTS, p = tid % NPTS;
        const float* k3 = kp + (a * NPTS + p) * 3;
        float x = k3[0], y = k3[1], z = k3[2];
        const float* M = proj + c * 16;
        float px = M[0]*x + M[1]*y + M[2]*z  + M[3];
        float py = M[4]*x + M[5]*y + M[6]*z  + M[7];
        float pd = fmaxf(M[8]*x + M[9]*y + M[10]*z + M[11], 1e-5f);
        float u = (px / pd) / wh[c*2+0] * 2.f - 1.f;
        float v = (py / pd) / wh[c*2+1] * 2.f - 1.f;
        s_uv[tid] = make_float2(u, v);
    }
    __syncthreads();

    {   // softmax per group (warp = group)
        const int g = tid >> 5, lane = tid & 31;
        float mx = -1e30f;
        for (int j = lane; j < NJ; j += 32) mx = fmaxf(mx, s_w[j * NG + g]);
        #pragma unroll
        for (int o = 16; o; o >>= 1) mx = fmaxf(mx, __shfl_xor_sync(0xffffffffu, mx, o));
        float sum = 0.f;
        float vals[10];
        int cnt = 0;
        for (int j = lane; j < NJ; j += 32) {
            float e = __expf(s_w[j * NG + g] - mx);
            vals[cnt++] = e;
            sum += e;
        }
        #pragma unroll
        for (int o = 16; o; o >>= 1) sum += __shfl_xor_sync(0xffffffffu, sum, o);
        float inv = 1.f / sum;
        cnt = 0;
        for (int j = lane; j < NJ; j += 32) s_w[j * NG + g] = vals[cnt++] * inv;
    }
    __syncthreads();

    // per-tap geometry; COMPACT: only taps with >=1 valid corner survive
    for (int t = tid; t < NJ; t += 256) {
        int p  = t % NPTS;
        int cl = t / NPTS;
        int l  = cl & 3;
        int c  = cl >> 2;
        int Wl = 176 >> l, Hl = 64 >> l;
        int HWl  = 11264 >> (2 * l);
        int loff = (l >= 1 ? 67584 : 0) + (l >= 2 ? 16896 : 0) + (l >= 3 ? 4224 : 0);

        float2 uv = s_uv[c * NPTS + p];
        float gx = (uv.x + 1.f) * (Wl * 0.5f) - 0.5f;
        float gy = (uv.y + 1.f) * (Hl * 0.5f) - 0.5f;
        float x0f = floorf(gx), y0f = floorf(gy);
        float wx1 = gx - x0f,  wy1 = gy - y0f;
        float wx0 = 1.f - wx1, wy0 = 1.f - wy1;
        int x0 = (int)x0f, y0 = (int)y0f;
        bool vx0 = (x0 >= 0) && (x0 <= Wl - 1);
        bool vx1 = (x0 + 1 >= 0) && (x0 + 1 <= Wl - 1);
        bool vy0 = (y0 >= 0) && (y0 <= Hl - 1);
        bool vy1 = (y0 + 1 >= 0) && (y0 + 1 <= Hl - 1);
        if (!((vx0 || vx1) && (vy0 || vy1))) continue;   // tap contributes 0

        int x0c = min(max(x0, 0), Wl - 1);
        int x1c = min(max(x0 + 1, 0), Wl - 1);
        int y0c = min(max(y0, 0), Hl - 1);
        int y1c = min(max(y0 + 1, 0), Hl - 1);

        int base = loff + c * HWl;
        int4 off;
        off.x = (base + y0c * Wl + x0c) * EMBED * 2;
        off.y = (base + y0c * Wl + x1c) * EMBED * 2;
        off.z = (base + y1c * Wl + x0c) * EMBED * 2;
        off.w = (base + y1c * Wl + x1c) * EMBED * 2;

        float g00 = (vx0 && vy0) ? wx0 * wy0 : 0.f;
        float g01 = (vx1 && vy0) ? wx1 * wy0 : 0.f;
        float g10 = (vx0 && vy1) ? wx0 * wy1 : 0.f;
        float g11 = (vx1 && vy1) ? wx1 * wy1 : 0.f;

        int idx = atomicAdd(&s_nv, 1);
        s_off[idx] = off;
        #pragma unroll
        for (int g = 0; g < NG; g++) {
            float wg = s_w[t * NG + g];
            __nv_bfloat162 lo = __floats2bfloat162_rn(g00 * wg, g01 * wg);
            __nv_bfloat162 hi = __floats2bfloat162_rn(g10 * wg, g11 * wg);
            s_cw[idx][g] = make_uint2(*(unsigned*)&lo, *(unsigned*)&hi);
        }
    }
    __syncthreads();
    const int nv = s_nv;

    // streaming loop: lane = 8 channels (uint4 loads), tg = tap-eighth
    const int lane = tid & 31;
    const int tg   = tid >> 5;
    const int ch   = lane * 8;
    const int g    = lane >> 2;
    const char* fb = (const char*)g_fmT + ch * 2;

    float acc[8] = {};
    #pragma unroll 2
    for (int i = tg; i < nv; i += 8) {
        int4 off = s_off[i];
        uint2 wp = s_cw[i][g];
        __nv_bfloat162 wlo = B2(wp.x), whi = B2(wp.y);
        __nv_bfloat162 w00 = __low2bfloat162(wlo), w01 = __high2bfloat162(wlo);
        __nv_bfloat162 w10 = __low2bfloat162(whi), w11 = __high2bfloat162(whi);

        uint4 q00 = __ldg((const uint4*)(fb + off.x));
        uint4 q01 = __ldg((const uint4*)(fb + off.y));
        uint4 q10 = __ldg((const uint4*)(fb + off.z));
        uint4 q11 = __ldg((const uint4*)(fb + off.w));

        __nv_bfloat162 b0 = __hmul2(B2(q00.x), w00);
        __nv_bfloat162 b1 = __hmul2(B2(q00.y), w00);
        __nv_bfloat162 b2 = __hmul2(B2(q00.z), w00);
        __nv_bfloat162 b3 = __hmul2(B2(q00.w), w00);
        b0 = __hfma2(B2(q01.x), w01, b0);
        b1 = __hfma2(B2(q01.y), w01, b1);
        b2 = __hfma2(B2(q01.z), w01, b2);
        b3 = __hfma2(B2(q01.w), w01, b3);
        b0 = __hfma2(B2(q10.x), w10, b0);
        b1 = __hfma2(B2(q10.y), w10, b1);
        b2 = __hfma2(B2(q10.z), w10, b2);
        b3 = __hfma2(B2(q10.w), w10, b3);
        b0 = __hfma2(B2(q11.x), w11, b0);
        b1 = __hfma2(B2(q11.y), w11, b1);
        b2 = __hfma2(B2(q11.z), w11, b2);
        b3 = __hfma2(B2(q11.w), w11, b3);

        float2 f0 = __bfloat1622float2(b0);
        float2 f1 = __bfloat1622float2(b1);
        float2 f2 = __bfloat1622float2(b2);
        float2 f3 = __bfloat1622float2(b3);
        acc[0] += f0.x; acc[1] += f0.y; acc[2] += f1.x; acc[3] += f1.y;
        acc[4] += f2.x; acc[5] += f2.y; acc[6] += f3.x; acc[7] += f3.y;
    }
    #pragma unroll
    for (int i = 0; i < 8; i++) s_part[tg][ch + i] = acc[i];
    __syncthreads();
    {
        float f = 0.f;
        #pragma unroll
        for (int k = 0; k < 8; k++) f += s_part[k][tid];
        s_f[tid] = f;
    }
    __syncthreads();

    // epilogue GEMV: out[a] = s_f @ Wout(bf16) + bias + inst
    const int j0 = lane * 8;
    const int kg = tg;
    float oa[8] = {};
    #pragma unroll 4
    for (int k = kg * 32; k < kg * 32 + 32; k++) {
        uint4 w = __ldg((const uint4*)(g_WoutB + k * EMBED + j0));
        float f = s_f[k];
        float2 w0 = __bfloat1622float2(B2(w.x));
        float2 w1 = __bfloat1622float2(B2(w.y));
        float2 w2 = __bfloat1622float2(B2(w.z));
        float2 w3 = __bfloat1622float2(B2(w.w));
        oa[0] += f * w0.x; oa[1] += f * w0.y;
        oa[2] += f * w1.x; oa[3] += f * w1.y;
        oa[4] += f * w2.x; oa[5] += f * w2.y;
        oa[6] += f * w3.x; oa[7] += f * w3.y;
    }
    __syncthreads();
    #pragma unroll
    for (int i = 0; i < 8; i++) s_part[kg][j0 + i] = oa[i];
    __syncthreads();
    {
        float v = 0.f;
        #pragma unroll
        for (int k = 0; k < 8; k++) v += s_part[k][tid];
        out[a * EMBED + tid] = v + bout[tid] + inst[a * EMBED + tid];
    }
}

// ---------------- launch ---------------------------------------------------
extern "C" void kernel_launch(void* const* d_in, const int* in_sizes, int n_in,
                              void* d_out, int out_size) {
    const float* inst = (const float*)d_in[0];
    const float* anch = (const float*)d_in[1];
    const float* kp   = (const float*)d_in[2];
    const float* fm0  = (const float*)d_in[3];
    const float* fm1  = (const float*)d_in[4];
    const float* fm2  = (const float*)d_in[5];
    const float* fm3  = (const float*)d_in[6];
    const float* proj = (const float*)d_in[7];
    const float* wh   = (const float*)d_in[8];
    const float* Ww   = (const float*)d_in[9];
    const float* bw   = (const float*)d_in[10];
    const float* Wo   = (const float*)d_in[11];
    const float* bo   = (const float*)d_in[12];
    float* out = (float*)d_out;

    k_transpose<<<dim3(PBTOT, 4, NCAM), dim3(32, 8)>>>(fm0, fm1, fm2, fm3);
    k_wcvt<<<EMBED * EMBED / 1024, 256>>>(Wo);
    k_gemm_tc<<<dim3(NW / GBN, (NA + GBM - 1) / GBM), 256>>>(inst, anch, Ww, bw);
    k_sample<<<NA, 256>>>(kp, proj, wh, inst, bo, out);
}

// round 7
// speedup vs baseline: 3.1093x; 1.1299x over previous
#include <cuda_runtime.h>
#include <cuda_bf16.h>
#include <mma.h>
using namespace nvcuda;

#define NA    900
#define EMBED 256
#define NG    8
#define NCAM  6
#define NLVL  4
#define NPTS  13
#define NJ    312
#define NW    2496

#define HW0 11264
#define HW1 2816
#define HW2 704
#define HW3 176
#define LOFF0 0
#define LOFF1 67584
#define LOFF2 84480
#define LOFF3 88704
#define TOTPX 89760
#define FMT_ELEMS (TOTPX * EMBED)

#define PB0 352
#define PB1 88
#define PB2 22
#define PB3 6
#define PBTOT 468

// ---------------- scratch ----------------
__device__ __nv_bfloat16 g_fmT[FMT_ELEMS];
__device__ float g_logits[NA * NW];
__device__ __nv_bfloat16 g_WoutB[EMBED * EMBED];

// ---------------- 1) fused transpose ---------------------------------------
__global__ __launch_bounds__(256) void k_transpose(const float* __restrict__ fm0,
                                                   const float* __restrict__ fm1,
                                                   const float* __restrict__ fm2,
                                                   const float* __restrict__ fm3) {
    __shared__ float tile[32][65];
    int bx = blockIdx.x;
    const float* fm;
    int HW, loff;
    if (bx < PB0)                  { fm = fm0; HW = HW0; loff = LOFF0; }
    else if (bx < PB0 + PB1)       { fm = fm1; HW = HW1; loff = LOFF1; bx -= PB0; }
    else if (bx < PB0 + PB1 + PB2) { fm = fm2; HW = HW2; loff = LOFF2; bx -= PB0 + PB1; }
    else                           { fm = fm3; HW = HW3; loff = LOFF3; bx -= PB0 + PB1 + PB2; }

    const int c   = blockIdx.z;
    const int ch0 = blockIdx.y * 64;
    const int px0 = bx * 32;
    const int tx = threadIdx.x, ty = threadIdx.y;   // (32, 8)

    int px = px0 + tx;
    if (px < HW) {
        #pragma unroll
        for (int k = 0; k < 8; k++)
            tile[tx][ty + 8 * k] = fm[(c * EMBED + ch0 + ty + 8 * k) * HW + px];
    }
    __syncthreads();
    #pragma unroll
    for (int k = 0; k < 4; k++) {
        int r  = ty + 8 * k;
        int pw = px0 + r;
        if (pw < HW) {
            __nv_bfloat162 v = __floats2bfloat162_rn(tile[r][2 * tx],
                                                     tile[r][2 * tx + 1]);
            *(__nv_bfloat162*)(g_fmT + (size_t)(loff + c * HW + pw) * EMBED
                               + ch0 + 2 * tx) = v;
        }
    }
}

// ---------------- 1b) Wout -> bf16 -----------------------------------------
__global__ __launch_bounds__(256) void k_wcvt(const float* __restrict__ Wout) {
    int t = (blockIdx.x * 256 + threadIdx.x) * 4;
    float4 v = *(const float4*)(Wout + t);
    __nv_bfloat162 lo = __floats2bfloat162_rn(v.x, v.y);
    __nv_bfloat162 hi = __floats2bfloat162_rn(v.z, v.w);
    *(uint2*)(g_WoutB + t) = make_uint2(*(unsigned*)&lo, *(unsigned*)&hi);
}

// ---------------- 2) weight GEMM: tf32 WMMA --------------------------------
#define GBM 64
#define GBN 64
#define GKB 32
#define ALDA (GKB + 8)
__global__ __launch_bounds__(256) void k_gemm_tc(const float* __restrict__ inst,
                                                 const float* __restrict__ anch,
                                                 const float* __restrict__ W,
                                                 const float* __restrict__ bias) {
    __shared__ float As[GBM][ALDA];
    __shared__ float Bs[GKB][GBN];
    __shared__ float Cs[GBM][GBN];

    const int tid  = threadIdx.x;
    const int warp = tid >> 5;
    const int wm   = warp >> 1;
    const int wn   = warp & 1;
    const int n0   = blockIdx.x * GBN;
    const int a0   = blockIdx.y * GBM;

    wmma::fragment<wmma::accumulator, 16, 16, 8, float> c0, c1;
    wmma::fill_fragment(c0, 0.0f);
    wmma::fill_fragment(c1, 0.0f);

    for (int k0 = 0; k0 < EMBED; k0 += GKB) {
        for (int t = tid; t < GBM * GKB / 4; t += 256) {
            int m  = t >> 3;
            int kc = (t & 7) * 4;
            float4 v = make_float4(0.f, 0.f, 0.f, 0.f);
            int ga = a0 + m;
            if (ga < NA) {
                float4 i4 = *(const float4*)(inst + ga * EMBED + k0 + kc);
                float4 a4 = *(const float4*)(anch + ga * EMBED + k0 + kc);
                v = make_float4(i4.x + a4.x, i4.y + a4.y, i4.z + a4.z, i4.w + a4.w);
            }
            *(float4*)&As[m][kc] = v;
        }
        for (int t = tid; t < GKB * GBN / 4; t += 256) {
            int kr = t >> 4;
            int nc = (t & 15) * 4;
            *(float4*)&Bs[kr][nc] = *(const float4*)(W + (k0 + kr) * NW + n0 + nc);
        }
        __syncthreads();
        #pragma unroll
        for (int kk = 0; kk < GKB; kk += 8) {
            wmma::fragment<wmma::matrix_a, 16, 16, 8, wmma::precision::tf32, wmma::row_major> af;
            wmma::fragment<wmma::matrix_b, 16, 16, 8, wmma::precision::tf32, wmma::row_major> bf0, bf1;
            wmma::load_matrix_sync(af, &As[wm * 16][kk], ALDA);
            wmma::load_matrix_sync(bf0, &Bs[kk][wn * 32], GBN);
            wmma::load_matrix_sync(bf1, &Bs[kk][wn * 32 + 16], GBN);
            #pragma unroll
            for (int i = 0; i < af.num_elements; i++)
                af.x[i] = wmma::__float_to_tf32(af.x[i]);
            #pragma unroll
            for (int i = 0; i < bf0.num_elements; i++) {
                bf0.x[i] = wmma::__float_to_tf32(bf0.x[i]);
                bf1.x[i] = wmma::__float_to_tf32(bf1.x[i]);
            }
            wmma::mma_sync(c0, af, bf0, c0);
            wmma::mma_sync(c1, af, bf1, c1);
        }
        __syncthreads();
    }
    wmma::store_matrix_sync(&Cs[wm * 16][wn * 32], c0, GBN, wmma::mem_row_major);
    wmma::store_matrix_sync(&Cs[wm * 16][wn * 32 + 16], c1, GBN, wmma::mem_row_major);
    __syncthreads();
    for (int t = tid; t < GBM * GBN / 4; t += 256) {
        int m  = t >> 4;
        int nc = (t & 15) * 4;
        int ga = a0 + m;
        if (ga >= NA) continue;
        float4 v = *(float4*)&Cs[m][nc];
        float4 bb = *(const float4*)(bias + n0 + nc);
        v.x += bb.x; v.y += bb.y; v.z += bb.z; v.w += bb.w;
        *(float4*)(g_logits + ga * NW + n0 + nc) = v;
    }
}

// ---------------- 3) fused uv + softmax + compacted sampling + GEMV --------
// s_mix is s_w (logits/softmax) in phases 1-2, then re-used as
// s_part[8][256] + s_f (at float offset 2048) in phases 3-4.
#define B2(u) (*(__nv_bfloat162*)&(u))
__global__ __launch_bounds__(256) void k_sample(const float* __restrict__ kp,
                                                const float* __restrict__ proj,
                                                const float* __restrict__ wh,
                                                const float* __restrict__ inst,
                                                const float* __restrict__ bout,
                                                float* __restrict__ out) {
    __shared__ __align__(16) float s_mix[NW];
    __shared__ float2 s_uv[NCAM * NPTS];
    __shared__ int4   s_off[NJ];
    __shared__ uint2  s_cw[NJ][NG];
    __shared__ int    s_nv;
    float* s_w = s_mix;
    float (*s_part)[EMBED] = (float(*)[EMBED])s_mix;
    float* s_f = s_mix + 2048;

    const int a = blockIdx.x;
    const int tid = threadIdx.x;

    if (tid == 0) s_nv = 0;
    {   // stage logits
        const float4* L4 = (const float4*)(g_logits + a * NW);
        float4* S4 = (float4*)s_w;
        for (int t = tid; t < NW / 4; t += 256) S4[t] = L4[t];
    }
    if (tid < NCAM * NPTS) {   // project key points
        int c = tid / NPTS, p = tid % NPTS;
        const float* k3 = kp + (a * NPTS + p) * 3;
        float x = k3[0], y = k3[1], z = k3[2];
        const float* M = proj + c * 16;
        float px = M[0]*x + M[1]*y + M[2]*z  + M[3];
        float py = M[4]*x + M[5]*y + M[6]*z  + M[7];
        float pd = fmaxf(M[8]*x + M[9]*y + M[10]*z + M[11], 1e-5f);
        float u = (px / pd) / wh[c*2+0] * 2.f - 1.f;
        float v = (py / pd) / wh[c*2+1] * 2.f - 1.f;
        s_uv[tid] = make_float2(u, v);
    }
    __syncthreads();

    {   // softmax per group (warp = group)
        const int g = tid >> 5, lane = tid & 31;
        float mx = -1e30f;
        for (int j = lane; j < NJ; j += 32) mx = fmaxf(mx, s_w[j * NG + g]);
        #pragma unroll
        for (int o = 16; o; o >>= 1) mx = fmaxf(mx, __shfl_xor_sync(0xffffffffu, mx, o));
        float sum = 0.f;
        float vals[10];
        int cnt = 0;
        for (int j = lane; j < NJ; j += 32) {
            float e = __expf(s_w[j * NG + g] - mx);
            vals[cnt++] = e;
            sum += e;
        }
        #pragma unroll
        for (int o = 16; o; o >>= 1) sum += __shfl_xor_sync(0xffffffffu, sum, o);
        float inv = 1.f / sum;
        cnt = 0;
        for (int j = lane; j < NJ; j += 32) s_w[j * NG + g] = vals[cnt++] * inv;
    }
    __syncthreads();

    // per-tap geometry; compact: only taps with >=1 valid corner survive
    for (int t = tid; t < NJ; t += 256) {
        int p  = t % NPTS;
        int cl = t / NPTS;
        int l  = cl & 3;
        int c  = cl >> 2;
        int Wl = 176 >> l, Hl = 64 >> l;
        int HWl  = 11264 >> (2 * l);
        int loff = (l >= 1 ? 67584 : 0) + (l >= 2 ? 16896 : 0) + (l >= 3 ? 4224 : 0);

        float2 uv = s_uv[c * NPTS + p];
        float gx = (uv.x + 1.f) * (Wl * 0.5f) - 0.5f;
        float gy = (uv.y + 1.f) * (Hl * 0.5f) - 0.5f;
        float x0f = floorf(gx), y0f = floorf(gy);
        float wx1 = gx - x0f,  wy1 = gy - y0f;
        float wx0 = 1.f - wx1, wy0 = 1.f - wy1;
        int x0 = (int)x0f, y0 = (int)y0f;
        bool vx0 = (x0 >= 0) && (x0 <= Wl - 1);
        bool vx1 = (x0 + 1 >= 0) && (x0 + 1 <= Wl - 1);
        bool vy0 = (y0 >= 0) && (y0 <= Hl - 1);
        bool vy1 = (y0 + 1 >= 0) && (y0 + 1 <= Hl - 1);
        if (!((vx0 || vx1) && (vy0 || vy1))) continue;

        int x0c = min(max(x0, 0), Wl - 1);
        int x1c = min(max(x0 + 1, 0), Wl - 1);
        int y0c = min(max(y0, 0), Hl - 1);
        int y1c = min(max(y0 + 1, 0), Hl - 1);

        int base = loff + c * HWl;
        int4 off;
        off.x = (base + y0c * Wl + x0c) * EMBED * 2;
        off.y = (base + y0c * Wl + x1c) * EMBED * 2;
        off.z = (base + y1c * Wl + x0c) * EMBED * 2;
        off.w = (base + y1c * Wl + x1c) * EMBED * 2;

        float g00 = (vx0 && vy0) ? wx0 * wy0 : 0.f;
        float g01 = (vx1 && vy0) ? wx1 * wy0 : 0.f;
        float g10 = (vx0 && vy1) ? wx0 * wy1 : 0.f;
        float g11 = (vx1 && vy1) ? wx1 * wy1 : 0.f;

        int idx = atomicAdd(&s_nv, 1);
        s_off[idx] = off;
        #pragma unroll
        for (int g = 0; g < NG; g++) {
            float wg = s_w[t * NG + g];
            __nv_bfloat162 lo = __floats2bfloat162_rn(g00 * wg, g01 * wg);
            __nv_bfloat162 hi = __floats2bfloat162_rn(g10 * wg, g11 * wg);
            s_cw[idx][g] = make_uint2(*(unsigned*)&lo, *(unsigned*)&hi);
        }
    }
    __syncthreads();           // s_w dead; s_part/s_f take over the buffer
    const int nv = s_nv;

    const int lane = tid & 31;
    const int tg   = tid >> 5;
    const int ch   = lane * 8;
    const int g    = lane >> 2;
    const char* fb = (const char*)g_fmT + ch * 2;

    float acc[8] = {};
    #pragma unroll 2
    for (int i = tg; i < nv; i += 8) {
        int4 off = s_off[i];
        uint2 wp = s_cw[i][g];
        __nv_bfloat162 wlo = B2(wp.x), whi = B2(wp.y);
        __nv_bfloat162 w00 = __low2bfloat162(wlo), w01 = __high2bfloat162(wlo);
        __nv_bfloat162 w10 = __low2bfloat162(whi), w11 = __high2bfloat162(whi);

        uint4 q00 = __ldg((const uint4*)(fb + off.x));
        uint4 q01 = __ldg((const uint4*)(fb + off.y));
        uint4 q10 = __ldg((const uint4*)(fb + off.z));
        uint4 q11 = __ldg((const uint4*)(fb + off.w));

        __nv_bfloat162 b0 = __hmul2(B2(q00.x), w00);
        __nv_bfloat162 b1 = __hmul2(B2(q00.y), w00);
        __nv_bfloat162 b2 = __hmul2(B2(q00.z), w00);
        __nv_bfloat162 b3 = __hmul2(B2(q00.w), w00);
        b0 = __hfma2(B2(q01.x), w01, b0);
        b1 = __hfma2(B2(q01.y), w01, b1);
        b2 = __hfma2(B2(q01.z), w01, b2);
        b3 = __hfma2(B2(q01.w), w01, b3);
        b0 = __hfma2(B2(q10.x), w10, b0);
        b1 = __hfma2(B2(q10.y), w10, b1);
        b2 = __hfma2(B2(q10.z), w10, b2);
        b3 = __hfma2(B2(q10.w), w10, b3);
        b0 = __hfma2(B2(q11.x), w11, b0);
        b1 = __hfma2(B2(q11.y), w11, b1);
        b2 = __hfma2(B2(q11.z), w11, b2);
        b3 = __hfma2(B2(q11.w), w11, b3);

        float2 f0 = __bfloat1622float2(b0);
        float2 f1 = __bfloat1622float2(b1);
        float2 f2 = __bfloat1622float2(b2);
        float2 f3 = __bfloat1622float2(b3);
        acc[0] += f0.x; acc[1] += f0.y; acc[2] += f1.x; acc[3] += f1.y;
        acc[4] += f2.x; acc[5] += f2.y; acc[6] += f3.x; acc[7] += f3.y;
    }
    #pragma unroll
    for (int i = 0; i < 8; i++) s_part[tg][ch + i] = acc[i];
    __syncthreads();
    {
        float f = 0.f;
        #pragma unroll
        for (int k = 0; k < 8; k++) f += s_part[k][tid];
        s_f[tid] = f;
    }
    __syncthreads();

    // epilogue GEMV: out[a] = s_f @ Wout(bf16) + bias + inst
    const int j0 = lane * 8;
    const int kg = tg;
    float oa[8] = {};
    #pragma unroll 4
    for (int k = kg * 32; k < kg * 32 + 32; k++) {
        uint4 w = __ldg((const uint4*)(g_WoutB + k * EMBED + j0));
        float f = s_f[k];
        float2 w0 = __bfloat1622float2(B2(w.x));
        float2 w1 = __bfloat1622float2(B2(w.y));
        float2 w2 = __bfloat1622float2(B2(w.z));
        float2 w3 = __bfloat1622float2(B2(w.w));
        oa[0] += f * w0.x; oa[1] += f * w0.y;
        oa[2] += f * w1.x; oa[3] += f * w1.y;
        oa[4] += f * w2.x; oa[5] += f * w2.y;
        oa[6] += f * w3.x; oa[7] += f * w3.y;
    }
    __syncthreads();
    #pragma unroll
    for (int i = 0; i < 8; i++) s_part[kg][j0 + i] = oa[i];
    __syncthreads();
    {
        float v = 0.f;
        #pragma unroll
        for (int k = 0; k < 8; k++) v += s_part[k][tid];
        out[a * EMBED + tid] = v + bout[tid] + inst[a * EMBED + tid];
    }
}

// ---------------- launch: fork gemm/wcvt parallel to transpose -------------
extern "C" void kernel_launch(void* const* d_in, const int* in_sizes, int n_in,
                              void* d_out, int out_size) {
    const float* inst = (const float*)d_in[0];
    const float* anch = (const float*)d_in[1];
    const float* kp   = (const float*)d_in[2];
    const float* fm0  = (const float*)d_in[3];
    const float* fm1  = (const float*)d_in[4];
    const float* fm2  = (const float*)d_in[5];
    const float* fm3  = (const float*)d_in[6];
    const float* proj = (const float*)d_in[7];
    const float* wh   = (const float*)d_in[8];
    const float* Ww   = (const float*)d_in[9];
    const float* bw   = (const float*)d_in[10];
    const float* Wo   = (const float*)d_in[11];
    const float* bo   = (const float*)d_in[12];
    float* out = (float*)d_out;

    static cudaStream_t s1 = nullptr;
    static cudaEvent_t eFork = nullptr, eJoin = nullptr;
    if (!s1) {
        cudaStreamCreateWithFlags(&s1, cudaStreamNonBlocking);
        cudaEventCreateWithFlags(&eFork, cudaEventDisableTiming);
        cudaEventCreateWithFlags(&eJoin, cudaEventDisableTiming);
    }

    cudaEventRecord(eFork, 0);
    cudaStreamWaitEvent(s1, eFork, 0);
    k_gemm_tc<<<dim3(NW / GBN, (NA + GBM - 1) / GBM), 256, 0, s1>>>(inst, anch, Ww, bw);
    k_wcvt<<<EMBED * EMBED / 1024, 256, 0, s1>>>(Wo);
    cudaEventRecord(eJoin, s1);

    k_transpose<<<dim3(PBTOT, 4, NCAM), dim3(32, 8)>>>(fm0, fm1, fm2, fm3);

    cudaStreamWaitEvent(0, eJoin, 0);
    k_sample<<<NA, 256>>>(kp, proj, wh, inst, bo, out);
}

// round 9
// speedup vs baseline: 3.1164x; 1.0023x over previous
#include <cuda_runtime.h>
#include <cuda_bf16.h>
#include <mma.h>
using namespace nvcuda;

#define NA    900
#define EMBED 256
#define NG    8
#define NCAM  6
#define NLVL  4
#define NPTS  13
#define NJ    312
#define NW    2496

#define HW0 11264
#define HW1 2816
#define HW2 704
#define HW3 176
#define LOFF0 0
#define LOFF1 67584
#define LOFF2 84480
#define LOFF3 88704
#define TOTPX 89760
#define FMT_ELEMS (TOTPX * EMBED)

#define PB0 352
#define PB1 88
#define PB2 22
#define PB3 6
#define PBTOT 468

// ---------------- scratch ----------------
__device__ __nv_bfloat16 g_fmT[FMT_ELEMS];
__device__ float g_logits[NA * NW];
__device__ __nv_bfloat16 g_WoutB[EMBED * EMBED];

// ---------------- 1) fused transpose ---------------------------------------
__global__ __launch_bounds__(256) void k_transpose(const float* __restrict__ fm0,
                                                   const float* __restrict__ fm1,
                                                   const float* __restrict__ fm2,
                                                   const float* __restrict__ fm3) {
    __shared__ float tile[32][65];
    int bx = blockIdx.x;
    const float* fm;
    int HW, loff;
    if (bx < PB0)                  { fm = fm0; HW = HW0; loff = LOFF0; }
    else if (bx < PB0 + PB1)       { fm = fm1; HW = HW1; loff = LOFF1; bx -= PB0; }
    else if (bx < PB0 + PB1 + PB2) { fm = fm2; HW = HW2; loff = LOFF2; bx -= PB0 + PB1; }
    else                           { fm = fm3; HW = HW3; loff = LOFF3; bx -= PB0 + PB1 + PB2; }

    const int c   = blockIdx.z;
    const int ch0 = blockIdx.y * 64;
    const int px0 = bx * 32;
    const int tx = threadIdx.x, ty = threadIdx.y;   // (32, 8)

    int px = px0 + tx;
    if (px < HW) {
        #pragma unroll
        for (int k = 0; k < 8; k++)
            tile[tx][ty + 8 * k] = fm[(c * EMBED + ch0 + ty + 8 * k) * HW + px];
    }
    __syncthreads();
    #pragma unroll
    for (int k = 0; k < 4; k++) {
        int r  = ty + 8 * k;
        int pw = px0 + r;
        if (pw < HW) {
            __nv_bfloat162 v = __floats2bfloat162_rn(tile[r][2 * tx],
                                                     tile[r][2 * tx + 1]);
            *(__nv_bfloat162*)(g_fmT + (size_t)(loff + c * HW + pw) * EMBED
                               + ch0 + 2 * tx) = v;
        }
    }
}

// ---------------- 1b) Wout -> bf16 -----------------------------------------
__global__ __launch_bounds__(256) void k_wcvt(const float* __restrict__ Wout) {
    int t = (blockIdx.x * 256 + threadIdx.x) * 4;
    float4 v = *(const float4*)(Wout + t);
    __nv_bfloat162 lo = __floats2bfloat162_rn(v.x, v.y);
    __nv_bfloat162 hi = __floats2bfloat162_rn(v.z, v.w);
    *(uint2*)(g_WoutB + t) = make_uint2(*(unsigned*)&lo, *(unsigned*)&hi);
}

// ---------------- 2) weight GEMM: tf32 WMMA --------------------------------
#define GBM 64
#define GBN 64
#define GKB 32
#define ALDA (GKB + 8)
__global__ __launch_bounds__(256) void k_gemm_tc(const float* __restrict__ inst,
                                                 const float* __restrict__ anch,
                                                 const float* __restrict__ W,
                                                 const float* __restrict__ bias) {
    __shared__ float As[GBM][ALDA];
    __shared__ float Bs[GKB][GBN];
    __shared__ float Cs[GBM][GBN];

    const int tid  = threadIdx.x;
    const int warp = tid >> 5;
    const int wm   = warp >> 1;
    const int wn   = warp & 1;
    const int n0   = blockIdx.x * GBN;
    const int a0   = blockIdx.y * GBM;

    wmma::fragment<wmma::accumulator, 16, 16, 8, float> c0, c1;
    wmma::fill_fragment(c0, 0.0f);
    wmma::fill_fragment(c1, 0.0f);

    for (int k0 = 0; k0 < EMBED; k0 += GKB) {
        for (int t = tid; t < GBM * GKB / 4; t += 256) {
            int m  = t >> 3;
            int kc = (t & 7) * 4;
            float4 v = make_float4(0.f, 0.f, 0.f, 0.f);
            int ga = a0 + m;
            if (ga < NA) {
                float4 i4 = *(const float4*)(inst + ga * EMBED + k0 + kc);
                float4 a4 = *(const float4*)(anch + ga * EMBED + k0 + kc);
                v = make_float4(i4.x + a4.x, i4.y + a4.y, i4.z + a4.z, i4.w + a4.w);
            }
            *(float4*)&As[m][kc] = v;
        }
        for (int t = tid; t < GKB * GBN / 4; t += 256) {
            int kr = t >> 4;
            int nc = (t & 15) * 4;
            *(float4*)&Bs[kr][nc] = *(const float4*)(W + (k0 + kr) * NW + n0 + nc);
        }
        __syncthreads();
        #pragma unroll
        for (int kk = 0; kk < GKB; kk += 8) {
            wmma::fragment<wmma::matrix_a, 16, 16, 8, wmma::precision::tf32, wmma::row_major> af;
            wmma::fragment<wmma::matrix_b, 16, 16, 8, wmma::precision::tf32, wmma::row_major> bf0, bf1;
            wmma::load_matrix_sync(af, &As[wm * 16][kk], ALDA);
            wmma::load_matrix_sync(bf0, &Bs[kk][wn * 32], GBN);
            wmma::load_matrix_sync(bf1, &Bs[kk][wn * 32 + 16], GBN);
            #pragma unroll
            for (int i = 0; i < af.num_elements; i++)
                af.x[i] = wmma::__float_to_tf32(af.x[i]);
            #pragma unroll
            for (int i = 0; i < bf0.num_elements; i++) {
                bf0.x[i] = wmma::__float_to_tf32(bf0.x[i]);
                bf1.x[i] = wmma::__float_to_tf32(bf1.x[i]);
            }
            wmma::mma_sync(c0, af, bf0, c0);
            wmma::mma_sync(c1, af, bf1, c1);
        }
        __syncthreads();
    }
    wmma::store_matrix_sync(&Cs[wm * 16][wn * 32], c0, GBN, wmma::mem_row_major);
    wmma::store_matrix_sync(&Cs[wm * 16][wn * 32 + 16], c1, GBN, wmma::mem_row_major);
    __syncthreads();
    for (int t = tid; t < GBM * GBN / 4; t += 256) {
        int m  = t >> 4;
        int nc = (t & 15) * 4;
        int ga = a0 + m;
        if (ga >= NA) continue;
        float4 v = *(float4*)&Cs[m][nc];
        float4 bb = *(const float4*)(bias + n0 + nc);
        v.x += bb.x; v.y += bb.y; v.z += bb.z; v.w += bb.w;
        *(float4*)(g_logits + ga * NW + n0 + nc) = v;
    }
}

// ---------------- 3) fused uv + softmax + compacted sampling + GEMV --------
// s_mix is s_w (softmax weights) through the main loop; afterwards the same
// storage becomes s_part[8][256] (+ s_f at float offset 2048). All reuse is
// fenced by __syncthreads().
#define B2(u) (*(__nv_bfloat162*)&(u))
__global__ __launch_bounds__(256, 7) void k_sample(const float* __restrict__ kp,
                                                   const float* __restrict__ proj,
                                                   const float* __restrict__ wh,
                                                   const float* __restrict__ inst,
                                                   const float* __restrict__ bout,
                                                   float* __restrict__ out) {
    __shared__ __align__(16) float s_mix[NW];    // 9984 B
    __shared__ float2 s_uv[NCAM * NPTS];         // 624 B
    __shared__ int4   s_off[NJ];                 // 4992 B
    __shared__ uint2  s_g4[NJ];                  // 2496 B  (4x bf16 geo weights)
    __shared__ int    s_tap[NJ];                 // 1248 B  (orig tap index)
    __shared__ int    s_nv;
    float* s_w = s_mix;
    float (*s_part)[EMBED] = (float(*)[EMBED])s_mix;
    float* s_f = s_mix + 2048;

    const int a = blockIdx.x;
    const int tid = threadIdx.x;

    if (tid == 0) s_nv = 0;
    {   // stage logits
        const float4* L4 = (const float4*)(g_logits + a * NW);
        float4* S4 = (float4*)s_w;
        for (int t = tid; t < NW / 4; t += 256) S4[t] = L4[t];
    }
    if (tid < NCAM * NPTS) {   // project key points
        int c = tid / NPTS, p = tid % NPTS;
        const float* k3 = kp + (a * NPTS + p) * 3;
        float x = k3[0], y = k3[1], z = k3[2];
        const float* M = proj + c * 16;
        float px = M[0]*x + M[1]*y + M[2]*z  + M[3];
        float py = M[4]*x + M[5]*y + M[6]*z  + M[7];
        float pd = fmaxf(M[8]*x + M[9]*y + M[10]*z + M[11], 1e-5f);
        float u = (px / pd) / wh[c*2+0] * 2.f - 1.f;
        float v = (py / pd) / wh[c*2+1] * 2.f - 1.f;
        s_uv[tid] = make_float2(u, v);
    }
    __syncthreads();

    {   // softmax per group (warp = group); result stays in s_w
        const int g = tid >> 5, lane = tid & 31;
        float mx = -1e30f;
        for (int j = lane; j < NJ; j += 32) mx = fmaxf(mx, s_w[j * NG + g]);
        #pragma unroll
        for (int o = 16; o; o >>= 1) mx = fmaxf(mx, __shfl_xor_sync(0xffffffffu, mx, o));
        float sum = 0.f;
        float vals[10];
        int cnt = 0;
        for (int j = lane; j < NJ; j += 32) {
            float e = __expf(s_w[j * NG + g] - mx);
            vals[cnt++] = e;
            sum += e;
        }
        #pragma unroll
        for (int o = 16; o; o >>= 1) sum += __shfl_xor_sync(0xffffffffu, sum, o);
        float inv = 1.f / sum;
        cnt = 0;
        for (int j = lane; j < NJ; j += 32) s_w[j * NG + g] = vals[cnt++] * inv;
    }
    __syncthreads();

    // per-tap geometry; compact: only taps with >=1 valid corner survive
    for (int t = tid; t < NJ; t += 256) {
        int p  = t % NPTS;
        int cl = t / NPTS;
        int l  = cl & 3;
        int c  = cl >> 2;
        int Wl = 176 >> l, Hl = 64 >> l;
        int HWl  = 11264 >> (2 * l);
        int loff = (l >= 1 ? 67584 : 0) + (l >= 2 ? 16896 : 0) + (l >= 3 ? 4224 : 0);

        float2 uv = s_uv[c * NPTS + p];
        float gx = (uv.x + 1.f) * (Wl * 0.5f) - 0.5f;
        float gy = (uv.y + 1.f) * (Hl * 0.5f) - 0.5f;
        float x0f = floorf(gx), y0f = floorf(gy);
        float wx1 = gx - x0f,  wy1 = gy - y0f;
        float wx0 = 1.f - wx1, wy0 = 1.f - wy1;
        int x0 = (int)x0f, y0 = (int)y0f;
        bool vx0 = (x0 >= 0) && (x0 <= Wl - 1);
        bool vx1 = (x0 + 1 >= 0) && (x0 + 1 <= Wl - 1);
        bool vy0 = (y0 >= 0) && (y0 <= Hl - 1);
        bool vy1 = (y0 + 1 >= 0) && (y0 + 1 <= Hl - 1);
        if (!((vx0 || vx1) && (vy0 || vy1))) continue;

        int x0c = min(max(x0, 0), Wl - 1);
        int x1c = min(max(x0 + 1, 0), Wl - 1);
        int y0c = min(max(y0, 0), Hl - 1);
        int y1c = min(max(y0 + 1, 0), Hl - 1);

        int base = loff + c * HWl;
        int4 off;
        off.x = (base + y0c * Wl + x0c) * EMBED * 2;
        off.y = (base + y0c * Wl + x1c) * EMBED * 2;
        off.z = (base + y1c * Wl + x0c) * EMBED * 2;
        off.w = (base + y1c * Wl + x1c) * EMBED * 2;

        float g00 = (vx0 && vy0) ? wx0 * wy0 : 0.f;
        float g01 = (vx1 && vy0) ? wx1 * wy0 : 0.f;
        float g10 = (vx0 && vy1) ? wx0 * wy1 : 0.f;
        float g11 = (vx1 && vy1) ? wx1 * wy1 : 0.f;

        int idx = atomicAdd(&s_nv, 1);
        s_off[idx] = off;
        s_tap[idx] = t * NG;
        __nv_bfloat162 lo = __floats2bfloat162_rn(g00, g01);
        __nv_bfloat162 hi = __floats2bfloat162_rn(g10, g11);
        s_g4[idx] = make_uint2(*(unsigned*)&lo, *(unsigned*)&hi);
    }
    __syncthreads();
    const int nv = s_nv;

    const int lane = tid & 31;
    const int tg   = tid >> 5;
    const int ch   = lane * 8;
    const int g    = lane >> 2;
    const char* fb = (const char*)g_fmT + ch * 2;

    float acc[8] = {};
    #pragma unroll 2
    for (int i = tg; i < nv; i += 8) {
        int4 off = s_off[i];
        uint2 gp = s_g4[i];
        float wsm = s_w[s_tap[i] + g];          // softmax weight, fp32
        __nv_bfloat162 glo = B2(gp.x), ghi = B2(gp.y);
        __nv_bfloat162 w00 = __low2bfloat162(glo), w01 = __high2bfloat162(glo);
        __nv_bfloat162 w10 = __low2bfloat162(ghi), w11 = __high2bfloat162(ghi);

        uint4 q00 = __ldg((const uint4*)(fb + off.x));
        uint4 q01 = __ldg((const uint4*)(fb + off.y));
        uint4 q10 = __ldg((const uint4*)(fb + off.z));
        uint4 q11 = __ldg((const uint4*)(fb + off.w));

        __nv_bfloat162 b0 = __hmul2(B2(q00.x), w00);
        __nv_bfloat162 b1 = __hmul2(B2(q00.y), w00);
        __nv_bfloat162 b2 = __hmul2(B2(q00.z), w00);
        __nv_bfloat162 b3 = __hmul2(B2(q00.w), w00);
        b0 = __hfma2(B2(q01.x), w01, b0);
        b1 = __hfma2(B2(q01.y), w01, b1);
        b2 = __hfma2(B2(q01.z), w01, b2);
        b3 = __hfma2(B2(q01.w), w01, b3);
        b0 = __hfma2(B2(q10.x), w10, b0);
        b1 = __hfma2(B2(q10.y), w10, b1);
        b2 = __hfma2(B2(q10.z), w10, b2);
        b3 = __hfma2(B2(q10.w), w10, b3);
        b0 = __hfma2(B2(q11.x), w11, b0);
        b1 = __hfma2(B2(q11.y), w11, b1);
        b2 = __hfma2(B2(q11.z), w11, b2);
        b3 = __hfma2(B2(q11.w), w11, b3);

        float2 f0 = __bfloat1622float2(b0);
        float2 f1 = __bfloat1622float2(b1);
        float2 f2 = __bfloat1622float2(b2);
        float2 f3 = __bfloat1622float2(b3);
        acc[0] = fmaf(wsm, f0.x, acc[0]); acc[1] = fmaf(wsm, f0.y, acc[1]);
        acc[2] = fmaf(wsm, f1.x, acc[2]); acc[3] = fmaf(wsm, f1.y, acc[3]);
        acc[4] = fmaf(wsm, f2.x, acc[4]); acc[5] = fmaf(wsm, f2.y, acc[5]);
        acc[6] = fmaf(wsm, f3.x, acc[6]); acc[7] = fmaf(wsm, f3.y, acc[7]);
    }
    __syncthreads();                 // s_w now dead; safe to alias as s_part
    #pragma unroll
    for (int i = 0; i < 8; i++) s_part[tg][ch + i] = acc[i];
    __syncthreads();
    {
        float f = 0.f;
        #pragma unroll
        for (int k = 0; k < 8; k++) f += s_part[k][tid];
        s_f[tid] = f;
    }
    __syncthreads();

    // epilogue GEMV: out[a] = s_f @ Wout(bf16) + bias + inst
    const int j0 = lane * 8;
    const int kg = tg;
    float oa[8] = {};
    #pragma unroll 4
    for (int k = kg * 32; k < kg * 32 + 32; k++) {
        uint4 w = __ldg((const uint4*)(g_WoutB + k * EMBED + j0));
        float f = s_f[k];
        float2 w0 = __bfloat1622float2(B2(w.x));
        float2 w1 = __bfloat1622float2(B2(w.y));
        float2 w2 = __bfloat1622float2(B2(w.z));
        float2 w3 = __bfloat1622float2(B2(w.w));
        oa[0] += f * w0.x; oa[1] += f * w0.y;
        oa[2] += f * w1.x; oa[3] += f * w1.y;
        oa[4] += f * w2.x; oa[5] += f * w2.y;
        oa[6] += f * w3.x; oa[7] += f * w3.y;
    }
    __syncthreads();
    #pragma unroll
    for (int i = 0; i < 8; i++) s_part[kg][j0 + i] = oa[i];
    __syncthreads();
    {
        float v = 0.f;
        #pragma unroll
        for (int k = 0; k < 8; k++) v += s_part[k][tid];
        out[a * EMBED + tid] = v + bout[tid] + inst[a * EMBED + tid];
    }
}

// ---------------- launch: fork gemm/wcvt parallel to transpose -------------
extern "C" void kernel_launch(void* const* d_in, const int* in_sizes, int n_in,
                              void* d_out, int out_size) {
    const float* inst = (const float*)d_in[0];
    const float* anch = (const float*)d_in[1];
    const float* kp   = (const float*)d_in[2];
    const float* fm0  = (const float*)d_in[3];
    const float* fm1  = (const float*)d_in[4];
    const float* fm2  = (const float*)d_in[5];
    const float* fm3  = (const float*)d_in[6];
    const float* proj = (const float*)d_in[7];
    const float* wh   = (const float*)d_in[8];
    const float* Ww   = (const float*)d_in[9];
    const float* bw   = (const float*)d_in[10];
    const float* Wo   = (const float*)d_in[11];
    const float* bo   = (const float*)d_in[12];
    float* out = (float*)d_out;

    static cudaStream_t s1 = nullptr;
    static cudaEvent_t eFork = nullptr, eJoin = nullptr;
    if (!s1) {
        cudaStreamCreateWithFlags(&s1, cudaStreamNonBlocking);
        cudaEventCreateWithFlags(&eFork, cudaEventDisableTiming);
        cudaEventCreateWithFlags(&eJoin, cudaEventDisableTiming);
    }

    cudaEventRecord(eFork, 0);
    cudaStreamWaitEvent(s1, eFork, 0);
    k_gemm_tc<<<dim3(NW / GBN, (NA + GBM - 1) / GBM), 256, 0, s1>>>(inst, anch, Ww, bw);
    k_wcvt<<<EMBED * EMBED / 1024, 256, 0, s1>>>(Wo);
    cudaEventRecord(eJoin, s1);

    k_transpose<<<dim3(PBTOT, 4, NCAM), dim3(32, 8)>>>(fm0, fm1, fm2, fm3);

    cudaStreamWaitEvent(0, eJoin, 0);
    k_sample<<<NA, 256>>>(kp, proj, wh, inst, bo, out);
}